// round 2
// baseline (speedup 1.0000x reference)
#include <cuda_runtime.h>
#include <math.h>

#define HH 1024
#define WW 1024
#define NHH 63
#define NP 3969
#define H1_PER 15000       // 12 cpair * 625 * 2
#define H2_PER 26460       // 30 cpair * 441 * 2
#define H3_PER 15000

typedef unsigned long long ull;

// Intermediates (channel-paired float2 layouts, stored as raw floats)
__device__ float g_h1[(size_t)NP * H1_PER];   // [n][cp12][625] float2
__device__ float g_h2[(size_t)NP * H2_PER];   // [n][cp30][441] float2
__device__ float g_h3[(size_t)NP * H3_PER];   // [n][cp12][625] float2
__device__ float g_p [(size_t)NP * 1024];
// Pre-packed paired weights
__device__ float2 g_w2pk [18000];  // [co60][kyx25][cp12] = (w[co][2cp][kyx], w[co][2cp+1][kyx])
__device__ float2 g_wd2pk[18000];  // [co24][ky5][kx5][cp30] = flipped deconv2 w pairs

__device__ __forceinline__ void fma2(ull &d, ull a, ull b) {
    asm("fma.rn.f32x2 %0, %1, %2, %0;" : "+l"(d) : "l"(a), "l"(b));
}
__device__ __forceinline__ float lo_f(ull u) { return __uint_as_float((unsigned)u); }
__device__ __forceinline__ float hi_f(ull u) { return __uint_as_float((unsigned)(u >> 32)); }
__device__ __forceinline__ float elu1(float v) { return v > 0.f ? v : expm1f(v); }

// ---------------------------------------------------------------------------
// K0: pack paired weight tables
// ---------------------------------------------------------------------------
__global__ void pack_kernel(const float* __restrict__ w2,   // conv2_w [60][24][5][5]
                            const float* __restrict__ wd2)  // deconv2_w [60][24][5][5]
{
    int j = blockIdx.x * blockDim.x + threadIdx.x;
    if (j < 18000) {
        // conv2: j = (co*25 + kyx)*12 + cp
        int cp = j % 12; int t = j / 12; int kyx = t % 25; int co = t / 25;
        g_w2pk[j] = make_float2(w2[co * 600 + (2 * cp) * 25 + kyx],
                                w2[co * 600 + (2 * cp + 1) * 25 + kyx]);
    } else if (j < 36000) {
        int i = j - 18000;
        // deconv2: i = (((co*5+ky)*5)+kx)*30 + cp ; value = w[ci][co][4-ky][4-kx]
        int cp = i % 30; int t = i / 30; int kx = t % 5; int t2 = t / 5;
        int ky = t2 % 5; int co = t2 / 5;
        int fidx = co * 25 + (4 - ky) * 5 + (4 - kx);
        g_wd2pk[i] = make_float2(wd2[(2 * cp) * 600 + fidx],
                                 wd2[(2 * cp + 1) * 600 + fidx]);
    }
}

// ---------------------------------------------------------------------------
// K1: conv1 (3D 2x8x8 VALID) + ELU, pairs over depth d. Output h1 paired over c.
// ---------------------------------------------------------------------------
__global__ void __launch_bounds__(512, 1)
conv1_kernel(const float* __restrict__ x1, const float* __restrict__ x2,
             const float* __restrict__ w,  // [24][1][2][8][8]
             const float* __restrict__ b,  // [24]
             float* __restrict__ h1p) {
    __shared__ float2 sP2[32][32];     // (x1, x2) pairs
    __shared__ float2 sW2[24 * 64];    // (w[c][d=0][kyx], w[c][d=1][kyx])
    __shared__ float sB[24];
    const int n = blockIdx.x;
    const int iy = n / NHH, ix = n % NHH;
    const int bd = blockDim.x;

    for (int i = threadIdx.x; i < 1024; i += bd) {
        int wy = i >> 5, wx = i & 31;
        int g = (iy * 16 + wy) * WW + ix * 16 + wx;
        sP2[wy][wx] = make_float2(x1[g], x2[g]);
    }
    for (int i = threadIdx.x; i < 1536; i += bd) {
        int c = i >> 6, rem = i & 63;
        sW2[i] = make_float2(w[c * 128 + rem], w[c * 128 + 64 + rem]);
    }
    if (threadIdx.x < 24) sB[threadIdx.x] = b[threadIdx.x];
    __syncthreads();

    const ull* sP = reinterpret_cast<const ull*>(&sP2[0][0]);
    const ull* sW = reinterpret_cast<const ull*>(sW2);

    for (int r = threadIdx.x; r < 600; r += bd) {
        int c = r / 25, oy = r % 25;
        float bias = sB[c];
#pragma unroll
        for (int half = 0; half < 2; half++) {
            const int x0 = half ? 13 : 0;
            const int W  = half ? 12 : 13;
            ull acc[13];
#pragma unroll
            for (int j = 0; j < 13; j++) acc[j] = 0ull;
#pragma unroll
            for (int ky = 0; ky < 8; ky++) {
                ull reg[20];
                const ull* row = sP + (oy + ky) * 32 + x0;
#pragma unroll
                for (int i = 0; i < 20; i++) if (i < W + 7) reg[i] = row[i];
                const ull* wr = sW + c * 64 + ky * 8;
#pragma unroll
                for (int kx = 0; kx < 8; kx++) {
                    ull wv = wr[kx];
#pragma unroll
                    for (int j = 0; j < 13; j++) if (j < W) fma2(acc[j], reg[j + kx], wv);
                }
            }
            float* outp = h1p + (size_t)n * H1_PER;
#pragma unroll
            for (int j = 0; j < 13; j++) if (j < W) {
                float v = elu1(lo_f(acc[j]) + hi_f(acc[j]) + bias);
                outp[((c >> 1) * 625 + oy * 25 + x0 + j) * 2 + (c & 1)] = v;
            }
        }
    }
}

// ---------------------------------------------------------------------------
// K2: conv2 (5x5 VALID, 24->60) + ReLU. Input channel-paired; weights via LDG pairs.
// smem = 12*625 float2 = 60000B
// ---------------------------------------------------------------------------
__global__ void __launch_bounds__(512, 1)
conv2_kernel(const float* __restrict__ h1p,
             const float* __restrict__ b,   // [60]
             float* __restrict__ h2p) {
    extern __shared__ ull sIn[];  // 7500 ull
    const int n = blockIdx.x;
    const int bd = blockDim.x;
    const ull* in = reinterpret_cast<const ull*>(h1p + (size_t)n * H1_PER);
    for (int i = threadIdx.x; i < 7500; i += bd) sIn[i] = in[i];
    __syncthreads();

    const ull* wpk = reinterpret_cast<const ull*>(g_w2pk);

    for (int r = threadIdx.x; r < 1260; r += bd) {
        int co = r / 21, y = r % 21;
        ull acc[21];
#pragma unroll
        for (int x = 0; x < 21; x++) acc[x] = 0ull;
        for (int cp = 0; cp < 12; cp++) {
#pragma unroll
            for (int ky = 0; ky < 5; ky++) {
                ull reg[25];
                const ull* row = sIn + cp * 625 + (y + ky) * 25;
#pragma unroll
                for (int i = 0; i < 25; i++) reg[i] = row[i];
#pragma unroll
                for (int kx = 0; kx < 5; kx++) {
                    ull wv = __ldg(&wpk[(co * 25 + ky * 5 + kx) * 12 + cp]);
#pragma unroll
                    for (int x = 0; x < 21; x++) fma2(acc[x], reg[x + kx], wv);
                }
            }
        }
        float bias = b[co];
        float* outp = h2p + (size_t)n * H2_PER;
#pragma unroll
        for (int x = 0; x < 21; x++) {
            float v = fmaxf(lo_f(acc[x]) + hi_f(acc[x]) + bias, 0.f);
            outp[((co >> 1) * 441 + y * 21 + x) * 2 + (co & 1)] = v;
        }
    }
}

// ---------------------------------------------------------------------------
// K3: deconv2 (transposed 5x5, 60->24) + ELU. Padded channel-paired input in smem.
// smem = 30*841 float2 = 201840B. 608 threads, 1 row/thread, 2 x-chunks.
// ---------------------------------------------------------------------------
__global__ void __launch_bounds__(608, 1)
deconv2_kernel(const float* __restrict__ h2p,
               const float* __restrict__ b,   // [24]
               float* __restrict__ h3p) {
    extern __shared__ ull sIn[];  // 30*841 = 25230 ull
    const int n = blockIdx.x;
    const int bd = blockDim.x;
    for (int i = threadIdx.x; i < 25230; i += bd) sIn[i] = 0ull;
    __syncthreads();
    const ull* in = reinterpret_cast<const ull*>(h2p + (size_t)n * H2_PER);
    for (int i = threadIdx.x; i < 13230; i += bd) {
        int cp = i / 441, rem = i % 441;
        int y = rem / 21, x = rem % 21;
        sIn[cp * 841 + (y + 4) * 29 + (x + 4)] = in[i];
    }
    __syncthreads();

    const ull* wpk = reinterpret_cast<const ull*>(g_wd2pk);
    const int t = threadIdx.x;
    if (t >= 600) return;
    const int co = t / 25, y = t % 25;
    const float bias = b[co];
    float* outp = h3p + (size_t)n * H3_PER;

#pragma unroll
    for (int half = 0; half < 2; half++) {
        const int x0 = half ? 13 : 0;
        const int W  = half ? 12 : 13;
        ull acc[13];
#pragma unroll
        for (int j = 0; j < 13; j++) acc[j] = 0ull;
        for (int cp = 0; cp < 30; cp++) {
#pragma unroll
            for (int ky = 0; ky < 5; ky++) {
                ull reg[17];
                const ull* row = sIn + cp * 841 + (y + ky) * 29 + x0;
#pragma unroll
                for (int i = 0; i < 17; i++) if (i < W + 4) reg[i] = row[i];
#pragma unroll
                for (int kx = 0; kx < 5; kx++) {
                    ull wv = __ldg(&wpk[((co * 5 + ky) * 5 + kx) * 30 + cp]);
#pragma unroll
                    for (int j = 0; j < 13; j++) if (j < W) fma2(acc[j], reg[j + kx], wv);
                }
            }
        }
#pragma unroll
        for (int j = 0; j < 13; j++) if (j < W) {
            float v = elu1(lo_f(acc[j]) + hi_f(acc[j]) + bias);
            outp[((co >> 1) * 625 + y * 25 + x0 + j) * 2 + (co & 1)] = v;
        }
    }
}

// ---------------------------------------------------------------------------
// K4: deconv1 (transposed 2x8x8, 24->1) fused with einsum+bias -> p
// channel-paired over ci. smem = 12*1521 float2 + 768 float2 = 152160B
// ---------------------------------------------------------------------------
__global__ void __launch_bounds__(512, 1)
deconv1_p_kernel(const float* __restrict__ h3p,
                 const float* __restrict__ w1,    // [24][1][2][8][8]
                 const float* __restrict__ b1,    // [1]
                 const float* __restrict__ lin_w, // [N][2]
                 const float* __restrict__ lin_b, // [N]
                 float* __restrict__ P) {
    extern __shared__ ull sm[];
    ull* sIn  = sm;            // 12*1521 = 18252 ull
    float2* sWf = reinterpret_cast<float2*>(sm + 18252);  // 768 float2
    const int n = blockIdx.x;
    const int bd = blockDim.x;
    const float lw0 = lin_w[2 * n], lw1 = lin_w[2 * n + 1];

    for (int i = threadIdx.x; i < 18252; i += bd) sIn[i] = 0ull;
    __syncthreads();
    const ull* in = reinterpret_cast<const ull*>(h3p + (size_t)n * H3_PER);
    for (int i = threadIdx.x; i < 7500; i += bd) {
        int cp = i / 625, rem = i % 625;
        int y = rem / 25, x = rem % 25;
        sIn[cp * 1521 + (y + 7) * 39 + (x + 7)] = in[i];
    }
    for (int i = threadIdx.x; i < 768; i += bd) {
        int cp = i >> 6, rem = i & 63;
        int ky = rem >> 3, kx = rem & 7;
        int f0 = (2 * cp) * 128 + (7 - ky) * 8 + (7 - kx);
        int f1 = (2 * cp + 1) * 128 + (7 - ky) * 8 + (7 - kx);
        sWf[i] = make_float2(lw0 * w1[f0] + lw1 * w1[f0 + 64],
                             lw0 * w1[f1] + lw1 * w1[f1 + 64]);
    }
    __syncthreads();

    const ull* sW = reinterpret_cast<const ull*>(sWf);
    const float cst = (lw0 + lw1) * b1[0] + lin_b[n];
    const int t = threadIdx.x;
    const int y = t >> 4;
    const int x0 = (t & 15) * 2;
    ull acc0 = 0ull, acc1 = 0ull;
    for (int cp = 0; cp < 12; cp++) {
#pragma unroll
        for (int ky = 0; ky < 8; ky++) {
            ull reg[9];
            const ull* row = sIn + cp * 1521 + (y + ky) * 39 + x0;
#pragma unroll
            for (int i = 0; i < 9; i++) reg[i] = row[i];
            const ull* wr = sW + cp * 64 + ky * 8;
#pragma unroll
            for (int kx = 0; kx < 8; kx++) {
                ull wv = wr[kx];
                fma2(acc0, reg[kx], wv);
                fma2(acc1, reg[kx + 1], wv);
            }
        }
    }
    float* outp = P + (size_t)n * 1024 + y * 32 + x0;
    outp[0] = lo_f(acc0) + hi_f(acc0) + cst;
    outp[1] = lo_f(acc1) + hi_f(acc1) + cst;
}

// ---------------------------------------------------------------------------
// K5: overlap-add scatter + final residual
// ---------------------------------------------------------------------------
__global__ void final_kernel(const float* __restrict__ x2,
                             const float* __restrict__ P,
                             const float* __restrict__ linear1_w,
                             float* __restrict__ out) {
    int idx = blockIdx.x * blockDim.x + threadIdx.x;
    if (idx >= HH * WW) return;
    int Y = idx >> 10, X = idx & 1023;
    float s = 0.f;
    int iy = Y >> 4, ix = X >> 4;
#pragma unroll
    for (int di = 0; di < 2; di++) {
        int i = iy - di;
        if (i < 0 || i > 62) continue;
        int py = Y - i * 16;
        if (py >= 32) continue;
#pragma unroll
        for (int dj = 0; dj < 2; dj++) {
            int j = ix - dj;
            if (j < 0 || j > 62) continue;
            int px = X - j * 16;
            if (px >= 32) continue;
            s += P[(size_t)(i * NHH + j) * 1024 + py * 32 + px];
        }
    }
    out[idx] = x2[idx] - s * linear1_w[0];
}

// ---------------------------------------------------------------------------
extern "C" void kernel_launch(void* const* d_in, const int* in_sizes, int n_in,
                              void* d_out, int out_size) {
    const float* x1        = (const float*)d_in[0];
    const float* x2        = (const float*)d_in[1];
    const float* conv1_w   = (const float*)d_in[2];
    const float* conv1_b   = (const float*)d_in[3];
    const float* conv2_w   = (const float*)d_in[4];
    const float* conv2_b   = (const float*)d_in[5];
    const float* deconv2_w = (const float*)d_in[6];
    const float* deconv2_b = (const float*)d_in[7];
    const float* deconv1_w = (const float*)d_in[8];
    const float* deconv1_b = (const float*)d_in[9];
    const float* lin_w     = (const float*)d_in[10];
    const float* lin_b     = (const float*)d_in[11];
    const float* linear1_w = (const float*)d_in[12];
    float* out = (float*)d_out;

    float *h1, *h2, *h3, *P;
    cudaGetSymbolAddress((void**)&h1, g_h1);
    cudaGetSymbolAddress((void**)&h2, g_h2);
    cudaGetSymbolAddress((void**)&h3, g_h3);
    cudaGetSymbolAddress((void**)&P,  g_p);

    const int smem2 = 7500 * 8;            // 60000
    const int smem3 = 25230 * 8;           // 201840
    const int smem4 = (18252 + 768) * 8;   // 152160
    cudaFuncSetAttribute(conv2_kernel,     cudaFuncAttributeMaxDynamicSharedMemorySize, smem2);
    cudaFuncSetAttribute(deconv2_kernel,   cudaFuncAttributeMaxDynamicSharedMemorySize, smem3);
    cudaFuncSetAttribute(deconv1_p_kernel, cudaFuncAttributeMaxDynamicSharedMemorySize, smem4);

    pack_kernel<<<(36000 + 255) / 256, 256>>>(conv2_w, deconv2_w);
    conv1_kernel<<<NP, 512>>>(x1, x2, conv1_w, conv1_b, h1);
    conv2_kernel<<<NP, 512, smem2>>>(h1, conv2_b, h2);
    deconv2_kernel<<<NP, 608, smem3>>>(h2, deconv2_b, h3);
    deconv1_p_kernel<<<NP, 512, smem4>>>(h3, deconv1_w, deconv1_b, lin_w, lin_b, P);
    final_kernel<<<(HH * WW + 255) / 256, 256>>>(x2, P, linear1_w, out);
}

// round 7
// speedup vs baseline: 1.2051x; 1.2051x over previous
#include <cuda_runtime.h>
#include <cuda_bf16.h>
#include <math.h>
#include <stdint.h>

#define HH 1024
#define WW 1024
#define NHH 63
#define NP 3969
#define H1_PER 15000
#define H2_PER 26460

typedef unsigned long long ull;

// -------- global intermediates (no allocation allowed) --------
__device__ uint32_t g_h1u[(size_t)NP * H1_PER];     // bf16 hi|lo<<16, [c24][625]
__device__ uint32_t g_h2u[(size_t)NP * H2_PER];     // bf16 hi|lo<<16, [c60][441]
__device__ float    g_part[(size_t)2 * NP * 15000]; // deconv2 partials [half][n][cp12][625]x2
__device__ float    g_p[(size_t)NP * 1024];
__device__ uint32_t g_BcHi[64 * 320], g_BcLo[64 * 320];        // conv2 B planes [n64][kp320]
__device__ uint32_t g_BdHi[2 * 24 * 384], g_BdLo[2 * 24 * 384];// deconv2 B [half][n24][kp384]

__device__ __forceinline__ float elu1(float v) { return v > 0.f ? v : expm1f(v); }
__device__ __forceinline__ uint32_t f32_to_hl(float v) {
    unsigned short h = __bfloat16_as_ushort(__float2bfloat16(v));
    float hf = __bfloat162float(__ushort_as_bfloat16(h));
    unsigned short l = __bfloat16_as_ushort(__float2bfloat16(v - hf));
    return (uint32_t)h | ((uint32_t)l << 16);
}
__device__ __forceinline__ void fma2(ull &d, ull a, ull b) {
    asm("fma.rn.f32x2 %0, %1, %2, %0;" : "+l"(d) : "l"(a), "l"(b));
}
__device__ __forceinline__ float lo_f(ull u) { return __uint_as_float((unsigned)u); }
__device__ __forceinline__ float hi_f(ull u) { return __uint_as_float((unsigned)(u >> 32)); }

// m16n8k16 bf16 MMA, fp32 accumulate (baseline PTX, works on sm_103 non-'a')
__device__ __forceinline__ void mma_bf16(float d[4], const uint32_t a[4],
                                         uint32_t b0, uint32_t b1) {
    asm("mma.sync.aligned.m16n8k16.row.col.f32.bf16.bf16.f32 "
        "{%0,%1,%2,%3}, {%4,%5,%6,%7}, {%8,%9}, {%0,%1,%2,%3};"
        : "+f"(d[0]), "+f"(d[1]), "+f"(d[2]), "+f"(d[3])
        : "r"(a[0]), "r"(a[1]), "r"(a[2]), "r"(a[3]), "r"(b0), "r"(b1));
}

// ---------------- K0: pack B planes ----------------
__global__ void pack_kernel(const float* __restrict__ w2, const float* __restrict__ wd2) {
    int j = blockIdx.x * blockDim.x + threadIdx.x;
    if (j < 20480) {
        // conv2: [row n][kp], k = ci*25 + kyx -> w2[n*600 + k]
        int r = j / 320, kp = j % 320;
        int k0 = 2 * kp;
        float v0 = (r < 60 && k0 < 600) ? w2[r * 600 + k0] : 0.f;
        float v1 = (r < 60 && k0 + 1 < 600) ? w2[r * 600 + k0 + 1] : 0.f;
        uint32_t h0 = f32_to_hl(v0), h1 = f32_to_hl(v1);
        g_BcHi[j] = __byte_perm(h0, h1, 0x5410);
        g_BcLo[j] = __byte_perm(h0, h1, 0x7632);
    } else if (j < 20480 + 18432) {
        int i = j - 20480;                 // [half][n24][kp384]
        int h = i / 9216, rem = i % 9216, r = rem / 384, kp = rem % 384;
        float v[2] = {0.f, 0.f};
#pragma unroll
        for (int d = 0; d < 2; d++) {
            int k = 2 * kp + d;
            if (k < 750) {
                int ci = h * 30 + k / 25, rr = k % 25, ky = rr / 5, kx = rr % 5;
                v[d] = wd2[ci * 600 + r * 25 + (4 - ky) * 5 + (4 - kx)];
            }
        }
        uint32_t h0 = f32_to_hl(v[0]), h1 = f32_to_hl(v[1]);
        g_BdHi[i] = __byte_perm(h0, h1, 0x5410);
        g_BdLo[i] = __byte_perm(h0, h1, 0x7632);
    }
}

// ---------------- K1: conv1 + ELU (FFMA2), out u32 hi/lo [c24][625] ----------------
__global__ void __launch_bounds__(512, 1)
conv1_kernel(const float* __restrict__ x1, const float* __restrict__ x2,
             const float* __restrict__ w, const float* __restrict__ b,
             uint32_t* __restrict__ h1u) {
    __shared__ float2 sP2[32][32];
    __shared__ float2 sW2[24 * 64];
    __shared__ float sB[24];
    const int n = blockIdx.x;
    const int iy = n / NHH, ix = n % NHH;
    const int bd = blockDim.x;
    for (int i = threadIdx.x; i < 1024; i += bd) {
        int wy = i >> 5, wx = i & 31;
        int g = (iy * 16 + wy) * WW + ix * 16 + wx;
        sP2[wy][wx] = make_float2(x1[g], x2[g]);
    }
    for (int i = threadIdx.x; i < 1536; i += bd) {
        int c = i >> 6, rem = i & 63;
        sW2[i] = make_float2(w[c * 128 + rem], w[c * 128 + 64 + rem]);
    }
    if (threadIdx.x < 24) sB[threadIdx.x] = b[threadIdx.x];
    __syncthreads();
    const ull* sP = reinterpret_cast<const ull*>(&sP2[0][0]);
    const ull* sW = reinterpret_cast<const ull*>(sW2);
    for (int r = threadIdx.x; r < 600; r += bd) {
        int c = r / 25, oy = r % 25;
        float bias = sB[c];
#pragma unroll
        for (int half = 0; half < 2; half++) {
            const int x0 = half ? 13 : 0;
            const int W  = half ? 12 : 13;
            ull acc[13];
#pragma unroll
            for (int j = 0; j < 13; j++) acc[j] = 0ull;
#pragma unroll
            for (int ky = 0; ky < 8; ky++) {
                ull reg[20];
                const ull* row = sP + (oy + ky) * 32 + x0;
#pragma unroll
                for (int i = 0; i < 20; i++) if (i < W + 7) reg[i] = row[i];
                const ull* wr = sW + c * 64 + ky * 8;
#pragma unroll
                for (int kx = 0; kx < 8; kx++) {
                    ull wv = wr[kx];
#pragma unroll
                    for (int j = 0; j < 13; j++) if (j < W) fma2(acc[j], reg[j + kx], wv);
                }
            }
            uint32_t* outp = h1u + (size_t)n * H1_PER;
#pragma unroll
            for (int j = 0; j < 13; j++) if (j < W) {
                float v = elu1(lo_f(acc[j]) + hi_f(acc[j]) + bias);
                outp[c * 625 + oy * 25 + x0 + j] = f32_to_hl(v);
            }
        }
    }
}

// ---------------- K2: conv2 via mma.sync. D[448,64]=A[448,640]xB^T ----------------
// smem u32: h1s[15532] kOff[640] BH[10496] BL[10496] = 37164 u32 = 148656 B
#define C2_SMEM 148656
__global__ void __launch_bounds__(448, 1)
conv2_mma_kernel(const uint32_t* __restrict__ h1g, const float* __restrict__ bias,
                 uint32_t* __restrict__ h2g) {
    extern __shared__ uint32_t s[];
    uint32_t* h1s = s;            // 15532 (incl. zero zone [15000,15532))
    uint32_t* kOff = s + 15532;
    uint32_t* BH = s + 16172;     // stride 164, 64 rows
    uint32_t* BL = s + 26668;
    const int n = blockIdx.x, tid = threadIdx.x;
    const int lane = tid & 31, wid = tid >> 5, gid = lane >> 2, tig = lane & 3;

    for (int i = tid; i < 15532; i += 448)
        h1s[i] = (i < 15000) ? h1g[(size_t)n * 15000 + i] : 0u;
    for (int k = tid; k < 640; k += 448) {
        uint32_t v = 15000u;
        if (k < 600) { int ci = k / 25, rr = k % 25; v = ci * 625 + (rr / 5) * 25 + (rr % 5); }
        kOff[k] = v;
    }
    int ro[2][2], mm[2][2];
#pragma unroll
    for (int t = 0; t < 2; t++) {
        int m = wid * 32 + t * 16 + gid;
        mm[t][0] = m;     ro[t][0] = (m / 21) * 25 + (m % 21);
        mm[t][1] = m + 8; ro[t][1] = ((m + 8) / 21) * 25 + ((m + 8) % 21);
    }
    float acc[2][8][4];
#pragma unroll
    for (int t = 0; t < 2; t++)
#pragma unroll
        for (int nt = 0; nt < 8; nt++)
#pragma unroll
            for (int j = 0; j < 4; j++) acc[t][nt][j] = 0.f;

    for (int half = 0; half < 2; half++) {
        __syncthreads();
        for (int i = tid; i < 10240; i += 448) {
            int r = i / 160, kp = i % 160;
            BH[r * 164 + kp] = g_BcHi[r * 320 + half * 160 + kp];
            BL[r * 164 + kp] = g_BcLo[r * 320 + half * 160 + kp];
        }
        __syncthreads();
        for (int kcl = 0; kcl < 20; kcl++) {
            int kb = half * 320 + kcl * 16 + 2 * tig;
            uint32_t ko0 = kOff[kb], ko1 = kOff[kb + 1], ko8 = kOff[kb + 8], ko9 = kOff[kb + 9];
            uint32_t aH[2][4], aL[2][4];
#pragma unroll
            for (int t = 0; t < 2; t++) {
                uint32_t e00 = h1s[ko0 + ro[t][0]], e01 = h1s[ko1 + ro[t][0]];
                uint32_t e10 = h1s[ko0 + ro[t][1]], e11 = h1s[ko1 + ro[t][1]];
                uint32_t e08 = h1s[ko8 + ro[t][0]], e09 = h1s[ko9 + ro[t][0]];
                uint32_t e18 = h1s[ko8 + ro[t][1]], e19 = h1s[ko9 + ro[t][1]];
                aH[t][0] = __byte_perm(e00, e01, 0x5410); aL[t][0] = __byte_perm(e00, e01, 0x7632);
                aH[t][1] = __byte_perm(e10, e11, 0x5410); aL[t][1] = __byte_perm(e10, e11, 0x7632);
                aH[t][2] = __byte_perm(e08, e09, 0x5410); aL[t][2] = __byte_perm(e08, e09, 0x7632);
                aH[t][3] = __byte_perm(e18, e19, 0x5410); aL[t][3] = __byte_perm(e18, e19, 0x7632);
            }
#pragma unroll
            for (int nt = 0; nt < 8; nt++) {
                int ba = (nt * 8 + gid) * 164 + kcl * 8 + tig;
                uint32_t b0h = BH[ba], b1h = BH[ba + 4];
                uint32_t b0l = BL[ba], b1l = BL[ba + 4];
#pragma unroll
                for (int t = 0; t < 2; t++) {
                    mma_bf16(acc[t][nt], aH[t], b0h, b1h);
                    mma_bf16(acc[t][nt], aL[t], b0h, b1h);
                    mma_bf16(acc[t][nt], aH[t], b0l, b1l);
                }
            }
        }
    }
    uint32_t* outb = h2g + (size_t)n * 26460;
#pragma unroll
    for (int t = 0; t < 2; t++)
#pragma unroll
        for (int nt = 0; nt < 8; nt++) {
            int n0 = nt * 8 + tig * 2;
#pragma unroll
            for (int h = 0; h < 2; h++) {
                int m = mm[t][h];
                if (m < 441) {
                    if (n0 < 60) {
                        float v = acc[t][nt][h * 2] + __ldg(&bias[n0]);
                        outb[n0 * 441 + m] = f32_to_hl(fmaxf(v, 0.f));
                    }
                    if (n0 + 1 < 60) {
                        float v = acc[t][nt][h * 2 + 1] + __ldg(&bias[n0 + 1]);
                        outb[(n0 + 1) * 441 + m] = f32_to_hl(fmaxf(v, 0.f));
                    }
                }
            }
        }
}

// ---------------- K3: deconv2 via mma.sync, K-split over 2 CTAs/patch ----------------
// smem u32: h2s[25970] kOff[768] BH[9312] BL[9312] = 45362 u32 = 181448 B
#define D2_SMEM 181448
__global__ void __launch_bounds__(640, 1)
deconv2_mma_kernel(const uint32_t* __restrict__ h2g, const float* __restrict__ bias,
                   float* __restrict__ part) {
    extern __shared__ uint32_t s[];
    uint32_t* h2s = s;            // padded [30][29][29] + zero tail to 25970
    uint32_t* kOff = s + 25970;
    uint32_t* BH = s + 26738;     // stride 388, 24 rows
    uint32_t* BL = s + 36050;
    const int cta = blockIdx.x, n = cta >> 1, half = cta & 1;
    const int tid = threadIdx.x, lane = tid & 31, wid = tid >> 5, gid = lane >> 2, tig = lane & 3;

    for (int i = tid; i < 25970; i += 640) h2s[i] = 0u;
    __syncthreads();
    for (int i = tid; i < 13230; i += 640) {
        int ci = i / 441, rem = i % 441, y = rem / 21, x = rem % 21;
        h2s[ci * 841 + (y + 4) * 29 + (x + 4)] =
            h2g[(size_t)n * 26460 + (half * 30 + ci) * 441 + rem];
    }
    for (int k = tid; k < 768; k += 640) {
        uint32_t v = 25230u;
        if (k < 750) { int ci = k / 25, rr = k % 25; v = ci * 841 + (rr / 5) * 29 + (rr % 5); }
        kOff[k] = v;
    }
    for (int i = tid; i < 9216; i += 640) {
        int r = i / 384, kp = i % 384;
        BH[r * 388 + kp] = g_BdHi[half * 9216 + i];
        BL[r * 388 + kp] = g_BdLo[half * 9216 + i];
    }
    int ro[2][2], mm[2][2];
#pragma unroll
    for (int t = 0; t < 2; t++) {
        int m = wid * 32 + t * 16 + gid;
        mm[t][0] = m;     ro[t][0] = (m / 25) * 29 + (m % 25);
        mm[t][1] = m + 8; ro[t][1] = ((m + 8) / 25) * 29 + ((m + 8) % 25);
    }
    __syncthreads();

    float acc[2][3][4];
#pragma unroll
    for (int t = 0; t < 2; t++)
#pragma unroll
        for (int nt = 0; nt < 3; nt++)
#pragma unroll
            for (int j = 0; j < 4; j++) acc[t][nt][j] = 0.f;

    for (int kcl = 0; kcl < 48; kcl++) {
        int kb = kcl * 16 + 2 * tig;
        uint32_t ko0 = kOff[kb], ko1 = kOff[kb + 1], ko8 = kOff[kb + 8], ko9 = kOff[kb + 9];
        uint32_t aH[2][4], aL[2][4];
#pragma unroll
        for (int t = 0; t < 2; t++) {
            uint32_t e00 = h2s[ko0 + ro[t][0]], e01 = h2s[ko1 + ro[t][0]];
            uint32_t e10 = h2s[ko0 + ro[t][1]], e11 = h2s[ko1 + ro[t][1]];
            uint32_t e08 = h2s[ko8 + ro[t][0]], e09 = h2s[ko9 + ro[t][0]];
            uint32_t e18 = h2s[ko8 + ro[t][1]], e19 = h2s[ko9 + ro[t][1]];
            aH[t][0] = __byte_perm(e00, e01, 0x5410); aL[t][0] = __byte_perm(e00, e01, 0x7632);
            aH[t][1] = __byte_perm(e10, e11, 0x5410); aL[t][1] = __byte_perm(e10, e11, 0x7632);
            aH[t][2] = __byte_perm(e08, e09, 0x5410); aL[t][2] = __byte_perm(e08, e09, 0x7632);
            aH[t][3] = __byte_perm(e18, e19, 0x5410); aL[t][3] = __byte_perm(e18, e19, 0x7632);
        }
#pragma unroll
        for (int nt = 0; nt < 3; nt++) {
            int ba = (nt * 8 + gid) * 388 + kcl * 8 + tig;
            uint32_t b0h = BH[ba], b1h = BH[ba + 4];
            uint32_t b0l = BL[ba], b1l = BL[ba + 4];
#pragma unroll
            for (int t = 0; t < 2; t++) {
                mma_bf16(acc[t][nt], aH[t], b0h, b1h);
                mma_bf16(acc[t][nt], aL[t], b0h, b1h);
                mma_bf16(acc[t][nt], aH[t], b0l, b1l);
            }
        }
    }
    float* pb = part + ((size_t)half * NP + n) * 15000;
#pragma unroll
    for (int t = 0; t < 2; t++)
#pragma unroll
        for (int nt = 0; nt < 3; nt++) {
            int n0 = nt * 8 + tig * 2;   // 0..22
#pragma unroll
            for (int h = 0; h < 2; h++) {
                int m = mm[t][h];
                if (m < 625) {
                    float v0 = acc[t][nt][h * 2]     + (half ? 0.f : __ldg(&bias[n0]));
                    float v1 = acc[t][nt][h * 2 + 1] + (half ? 0.f : __ldg(&bias[n0 + 1]));
                    reinterpret_cast<float2*>(pb)[(n0 >> 1) * 625 + m] = make_float2(v0, v1);
                }
            }
        }
}

// ---------------- K4: reduce partials + ELU + deconv1 + einsum + bias (FFMA2) ----------------
__global__ void __launch_bounds__(512, 1)
deconv1_p_kernel(const float* __restrict__ part, const float* __restrict__ w1,
                 const float* __restrict__ b1, const float* __restrict__ lin_w,
                 const float* __restrict__ lin_b, float* __restrict__ P) {
    extern __shared__ ull sm[];
    ull* sIn = sm;  // 12*1521
    float2* sWf = reinterpret_cast<float2*>(sm + 18252);
    const int n = blockIdx.x;
    const int bd = blockDim.x;
    const float lw0 = lin_w[2 * n], lw1 = lin_w[2 * n + 1];
    for (int i = threadIdx.x; i < 18252; i += bd) sIn[i] = 0ull;
    __syncthreads();
    const float2* p0 = reinterpret_cast<const float2*>(part + (size_t)n * 15000);
    const float2* p1 = reinterpret_cast<const float2*>(part + ((size_t)NP + n) * 15000);
    for (int i = threadIdx.x; i < 7500; i += bd) {
        int cp = i / 625, rem = i % 625;
        int y = rem / 25, x = rem % 25;
        float2 a = p0[i], b = p1[i];
        float vx = elu1(a.x + b.x), vy = elu1(a.y + b.y);
        sIn[cp * 1521 + (y + 7) * 39 + (x + 7)] =
            ((ull)__float_as_uint(vy) << 32) | (ull)__float_as_uint(vx);
    }
    for (int i = threadIdx.x; i < 768; i += bd) {
        int cp = i >> 6, rem = i & 63;
        int ky = rem >> 3, kx = rem & 7;
        int f0 = (2 * cp) * 128 + (7 - ky) * 8 + (7 - kx);
        int f1 = (2 * cp + 1) * 128 + (7 - ky) * 8 + (7 - kx);
        sWf[i] = make_float2(lw0 * w1[f0] + lw1 * w1[f0 + 64],
                             lw0 * w1[f1] + lw1 * w1[f1 + 64]);
    }
    __syncthreads();
    const ull* sW = reinterpret_cast<const ull*>(sWf);
    const float cst = (lw0 + lw1) * b1[0] + lin_b[n];
    const int t = threadIdx.x;
    const int y = t >> 4;
    const int x0 = (t & 15) * 2;
    ull acc0 = 0ull, acc1 = 0ull;
    for (int cp = 0; cp < 12; cp++) {
#pragma unroll
        for (int ky = 0; ky < 8; ky++) {
            ull reg[9];
            const ull* row = sIn + cp * 1521 + (y + ky) * 39 + x0;
#pragma unroll
            for (int i = 0; i < 9; i++) reg[i] = row[i];
            const ull* wr = sW + cp * 64 + ky * 8;
#pragma unroll
            for (int kx = 0; kx < 8; kx++) {
                ull wv = wr[kx];
                fma2(acc0, reg[kx], wv);
                fma2(acc1, reg[kx + 1], wv);
            }
        }
    }
    float* outp = P + (size_t)n * 1024 + y * 32 + x0;
    outp[0] = lo_f(acc0) + hi_f(acc0) + cst;
    outp[1] = lo_f(acc1) + hi_f(acc1) + cst;
}

// ---------------- K5: overlap-add + residual ----------------
__global__ void final_kernel(const float* __restrict__ x2, const float* __restrict__ P,
                             const float* __restrict__ linear1_w, float* __restrict__ out) {
    int idx = blockIdx.x * blockDim.x + threadIdx.x;
    if (idx >= HH * WW) return;
    int Y = idx >> 10, X = idx & 1023;
    float s = 0.f;
    int iy = Y >> 4, ix = X >> 4;
#pragma unroll
    for (int di = 0; di < 2; di++) {
        int i = iy - di;
        if (i < 0 || i > 62) continue;
        int py = Y - i * 16;
        if (py >= 32) continue;
#pragma unroll
        for (int dj = 0; dj < 2; dj++) {
            int j = ix - dj;
            if (j < 0 || j > 62) continue;
            int px = X - j * 16;
            if (px >= 32) continue;
            s += P[(size_t)(i * NHH + j) * 1024 + py * 32 + px];
        }
    }
    out[idx] = x2[idx] - s * linear1_w[0];
}

// ---------------------------------------------------------------------------
extern "C" void kernel_launch(void* const* d_in, const int* in_sizes, int n_in,
                              void* d_out, int out_size) {
    const float* x1        = (const float*)d_in[0];
    const float* x2        = (const float*)d_in[1];
    const float* conv1_w   = (const float*)d_in[2];
    const float* conv1_b   = (const float*)d_in[3];
    const float* conv2_w   = (const float*)d_in[4];
    const float* conv2_b   = (const float*)d_in[5];
    const float* deconv2_w = (const float*)d_in[6];
    const float* deconv2_b = (const float*)d_in[7];
    const float* deconv1_w = (const float*)d_in[8];
    const float* deconv1_b = (const float*)d_in[9];
    const float* lin_w     = (const float*)d_in[10];
    const float* lin_b     = (const float*)d_in[11];
    const float* linear1_w = (const float*)d_in[12];
    float* out = (float*)d_out;

    uint32_t *h1u, *h2u;
    float *part, *P;
    cudaGetSymbolAddress((void**)&h1u,  g_h1u);
    cudaGetSymbolAddress((void**)&h2u,  g_h2u);
    cudaGetSymbolAddress((void**)&part, g_part);
    cudaGetSymbolAddress((void**)&P,    g_p);

    const int smem4 = (18252 + 768) * 8;
    cudaFuncSetAttribute(conv2_mma_kernel,   cudaFuncAttributeMaxDynamicSharedMemorySize, C2_SMEM);
    cudaFuncSetAttribute(deconv2_mma_kernel, cudaFuncAttributeMaxDynamicSharedMemorySize, D2_SMEM);
    cudaFuncSetAttribute(deconv1_p_kernel,   cudaFuncAttributeMaxDynamicSharedMemorySize, smem4);

    pack_kernel<<<(20480 + 18432 + 255) / 256, 256>>>(conv2_w, deconv2_w);
    conv1_kernel<<<NP, 512>>>(x1, x2, conv1_w, conv1_b, h1u);
    conv2_mma_kernel<<<NP, 448, C2_SMEM>>>(h1u, conv2_b, h2u);
    deconv2_mma_kernel<<<NP * 2, 640, D2_SMEM>>>(h2u, deconv2_b, part);
    deconv1_p_kernel<<<NP, 512, smem4>>>(part, deconv1_w, deconv1_b, lin_w, lin_b, P);
    final_kernel<<<(HH * WW + 255) / 256, 256>>>(x2, P, linear1_w, out);
}

// round 8
// speedup vs baseline: 2.7079x; 2.2471x over previous
#include <cuda_runtime.h>
#include <cuda_bf16.h>
#include <math.h>
#include <stdint.h>

#define HH 1024
#define WW 1024
#define NHH 63
#define NP 3969
#define W1F 1017              // H1_full dim
#define W2F 1013              // H2_full dim
#define H1SZ (W1F * W1F)      // 1034289
#define H2SZ (W2F * W2F)      // 1026169

typedef unsigned long long ull;

// -------- global intermediates --------
__device__ uint32_t g_H1[(size_t)24 * H1SZ];      // bf16 hi|lo<<16 full-image conv1 out
__device__ uint32_t g_H2[(size_t)60 * H2SZ];      // bf16 hi|lo<<16 full-image conv2 out
__device__ float    g_part[(size_t)2 * NP * 15000];
__device__ float    g_p[(size_t)NP * 1024];
__device__ uint2    g_Bc2H[40 * 8 * 32], g_Bc2L[40 * 8 * 32];     // conv2 B frags
__device__ uint2    g_Bd2H[2 * 48 * 3 * 32], g_Bd2L[2 * 48 * 3 * 32]; // deconv2 B frags

__device__ __forceinline__ float elu1(float v) { return v > 0.f ? v : expm1f(v); }
__device__ __forceinline__ uint32_t f32_to_hl(float v) {
    unsigned short h = __bfloat16_as_ushort(__float2bfloat16(v));
    float hf = __bfloat162float(__ushort_as_bfloat16(h));
    unsigned short l = __bfloat16_as_ushort(__float2bfloat16(v - hf));
    return (uint32_t)h | ((uint32_t)l << 16);
}
__device__ __forceinline__ void fma2(ull &d, ull a, ull b) {
    asm("fma.rn.f32x2 %0, %1, %2, %0;" : "+l"(d) : "l"(a), "l"(b));
}
__device__ __forceinline__ float lo_f(ull u) { return __uint_as_float((unsigned)u); }
__device__ __forceinline__ float hi_f(ull u) { return __uint_as_float((unsigned)(u >> 32)); }

__device__ __forceinline__ void mma_bf16(float d[4], const uint32_t a[4],
                                         uint32_t b0, uint32_t b1) {
    asm("mma.sync.aligned.m16n8k16.row.col.f32.bf16.bf16.f32 "
        "{%0,%1,%2,%3}, {%4,%5,%6,%7}, {%8,%9}, {%0,%1,%2,%3};"
        : "+f"(d[0]), "+f"(d[1]), "+f"(d[2]), "+f"(d[3])
        : "r"(a[0]), "r"(a[1]), "r"(a[2]), "r"(a[3]), "r"(b0), "r"(b1));
}

// ---------------- K0: pack B fragment tables ----------------
__global__ void pack_kernel(const float* __restrict__ w2, const float* __restrict__ wd2) {
    int j = blockIdx.x * blockDim.x + threadIdx.x;
    if (j < 10240) {
        // conv2: idx = (kcl*8+nt)*32+lane
        int lane = j & 31, nt = (j >> 5) & 7, kcl = j >> 8;
        int gid = lane >> 2, tig = lane & 3;
        int n = nt * 8 + gid;
        uint32_t sh[2], sl[2];
#pragma unroll
        for (int s = 0; s < 2; s++) {
            int k = kcl * 16 + 2 * tig + s * 8;
            float v0 = (n < 60 && k < 600) ? w2[n * 600 + k] : 0.f;
            float v1 = (n < 60 && k + 1 < 600) ? w2[n * 600 + k + 1] : 0.f;
            uint32_t h0 = f32_to_hl(v0), h1 = f32_to_hl(v1);
            sh[s] = __byte_perm(h0, h1, 0x5410);
            sl[s] = __byte_perm(h0, h1, 0x7632);
        }
        g_Bc2H[j] = make_uint2(sh[0], sh[1]);
        g_Bc2L[j] = make_uint2(sl[0], sl[1]);
    } else if (j < 10240 + 9216) {
        int i = j - 10240;   // idx = ((half*48+kcl)*3+nt)*32+lane
        int lane = i & 31, nt = (i >> 5) % 3, kcl = (i / 96) % 48, half = i / 4608;
        int gid = lane >> 2, tig = lane & 3;
        int r = nt * 8 + gid;   // < 24
        uint32_t sh[2], sl[2];
#pragma unroll
        for (int s = 0; s < 2; s++) {
            int k = kcl * 16 + 2 * tig + s * 8;
            float v0 = 0.f, v1 = 0.f;
            if (k < 750) {
                int ci = half * 30 + k / 25, rr = k % 25, ky = rr / 5, kx = rr % 5;
                v0 = wd2[ci * 600 + r * 25 + (4 - ky) * 5 + (4 - kx)];
            }
            if (k + 1 < 750) {
                int k1 = k + 1, ci = half * 30 + k1 / 25, rr = k1 % 25, ky = rr / 5, kx = rr % 5;
                v1 = wd2[ci * 600 + r * 25 + (4 - ky) * 5 + (4 - kx)];
            }
            uint32_t h0 = f32_to_hl(v0), h1 = f32_to_hl(v1);
            sh[s] = __byte_perm(h0, h1, 0x5410);
            sl[s] = __byte_perm(h0, h1, 0x7632);
        }
        g_Bd2H[i] = make_uint2(sh[0], sh[1]);
        g_Bd2L[i] = make_uint2(sl[0], sl[1]);
    }
}

// ---------------- K1: conv1 full-image (FFMA2) -> H1 ----------------
__global__ void __launch_bounds__(256)
conv1_full_kernel(const float* __restrict__ x1, const float* __restrict__ x2,
                  const float* __restrict__ w, const float* __restrict__ b,
                  uint32_t* __restrict__ H1) {
    __shared__ float2 sImg[23 * 72];
    __shared__ float2 sW2[24 * 64];
    __shared__ float sB[24];
    const int gy0 = blockIdx.y * 16, gx0 = blockIdx.x * 64;
    const int tid = threadIdx.x;
    for (int i = tid; i < 23 * 72; i += 256) {
        int r = i / 72, c = i % 72;
        int gy = gy0 + r, gx = gx0 + c;
        float2 v = make_float2(0.f, 0.f);
        if (c < 71 && gy < 1024 && gx < 1024) {
            int g = gy * 1024 + gx;
            v = make_float2(x1[g], x2[g]);
        }
        sImg[i] = v;
    }
    for (int i = tid; i < 1536; i += 256) {
        int c = i >> 6, rem = i & 63;
        sW2[i] = make_float2(w[c * 128 + rem], w[c * 128 + 64 + rem]);
    }
    if (tid < 24) sB[tid] = b[tid];
    __syncthreads();
    const ull* sP = reinterpret_cast<const ull*>(sImg);
    const ull* sW = reinterpret_cast<const ull*>(sW2);
    const int y = tid >> 4, x0 = (tid & 15) * 4;
    const int gy = gy0 + y;
    for (int c0 = 0; c0 < 24; c0 += 4) {
        ull acc[4][4];
#pragma unroll
        for (int cc = 0; cc < 4; cc++)
#pragma unroll
            for (int j = 0; j < 4; j++) acc[cc][j] = 0ull;
#pragma unroll
        for (int ky = 0; ky < 8; ky++) {
            ull reg[11];
            const ull* row = sP + (y + ky) * 72 + x0;
#pragma unroll
            for (int i = 0; i < 11; i++) reg[i] = row[i];
#pragma unroll
            for (int cc = 0; cc < 4; cc++) {
                const ull* wr = sW + (c0 + cc) * 64 + ky * 8;
#pragma unroll
                for (int kx = 0; kx < 8; kx++) {
                    ull wv = wr[kx];
#pragma unroll
                    for (int j = 0; j < 4; j++) fma2(acc[cc][j], reg[j + kx], wv);
                }
            }
        }
        if (gy < W1F) {
#pragma unroll
            for (int cc = 0; cc < 4; cc++) {
                float bias = sB[c0 + cc];
#pragma unroll
                for (int j = 0; j < 4; j++) {
                    int gx = gx0 + x0 + j;
                    if (gx < W1F) {
                        float v = elu1(lo_f(acc[cc][j]) + hi_f(acc[cc][j]) + bias);
                        H1[(size_t)(c0 + cc) * H1SZ + gy * W1F + gx] = f32_to_hl(v);
                    }
                }
            }
        }
    }
}

// ---------------- K2: conv2 full-image GEMM (mma.sync) -> H2 ----------------
// CTA: 256 thr, M=256 (2 img rows x 128 cols), N=64, K=640.
// smem u32: sCrop[19008] + zero zone to 19272 + kOff[640] = 19912 u32 = 79648 B
#define C2_SMEM 79648
__global__ void __launch_bounds__(256, 2)
conv2_full_kernel(const uint32_t* __restrict__ H1, const float* __restrict__ bias,
                  uint32_t* __restrict__ H2) {
    extern __shared__ uint32_t s[];
    uint32_t* kOff = s + 19272;
    const int bid = blockIdx.x;
    const int by = bid >> 3, bx = bid & 7;
    const int gy0 = by * 2, gx0 = bx * 128;
    const int tid = threadIdx.x, lane = tid & 31, wid = tid >> 5;
    const int gid = lane >> 2, tig = lane & 3;

    for (int i = tid; i < 19272; i += 256) {
        uint32_t v = 0u;
        if (i < 19008) {
            int ci = i / 792, rem = i % 792, r = rem / 132, c = rem % 132;
            int gy = gy0 + r, gx = gx0 + c;
            if (gy < W1F && gx < W1F) v = H1[(size_t)ci * H1SZ + gy * W1F + gx];
        }
        s[i] = v;
    }
    for (int k = tid; k < 640; k += 256) {
        uint32_t v = 19008u;
        if (k < 600) { int ci = k / 25, rr = k % 25; v = ci * 792 + (rr / 5) * 132 + (rr % 5); }
        kOff[k] = v;
    }
    int ro[2][2], mm[2][2];
#pragma unroll
    for (int t = 0; t < 2; t++)
#pragma unroll
        for (int h = 0; h < 2; h++) {
            int m = wid * 32 + t * 16 + gid + h * 8;
            mm[t][h] = m;
            ro[t][h] = (m >> 7) * 132 + (m & 127);
        }
    __syncthreads();

    float acc[2][8][4];
#pragma unroll
    for (int t = 0; t < 2; t++)
#pragma unroll
        for (int nt = 0; nt < 8; nt++)
#pragma unroll
            for (int j = 0; j < 4; j++) acc[t][nt][j] = 0.f;

    for (int kcl = 0; kcl < 40; kcl++) {
        int kb = kcl * 16 + 2 * tig;
        uint2 ko01 = *reinterpret_cast<const uint2*>(&kOff[kb]);
        uint2 ko89 = *reinterpret_cast<const uint2*>(&kOff[kb + 8]);
        uint32_t aH[2][4], aL[2][4];
#pragma unroll
        for (int t = 0; t < 2; t++) {
            uint32_t e00 = s[ko01.x + ro[t][0]], e01 = s[ko01.y + ro[t][0]];
            uint32_t e10 = s[ko01.x + ro[t][1]], e11 = s[ko01.y + ro[t][1]];
            uint32_t e08 = s[ko89.x + ro[t][0]], e09 = s[ko89.y + ro[t][0]];
            uint32_t e18 = s[ko89.x + ro[t][1]], e19 = s[ko89.y + ro[t][1]];
            aH[t][0] = __byte_perm(e00, e01, 0x5410); aL[t][0] = __byte_perm(e00, e01, 0x7632);
            aH[t][1] = __byte_perm(e10, e11, 0x5410); aL[t][1] = __byte_perm(e10, e11, 0x7632);
            aH[t][2] = __byte_perm(e08, e09, 0x5410); aL[t][2] = __byte_perm(e08, e09, 0x7632);
            aH[t][3] = __byte_perm(e18, e19, 0x5410); aL[t][3] = __byte_perm(e18, e19, 0x7632);
        }
#pragma unroll
        for (int nt = 0; nt < 8; nt++) {
            uint2 bh = __ldg(&g_Bc2H[(kcl * 8 + nt) * 32 + lane]);
            uint2 bl = __ldg(&g_Bc2L[(kcl * 8 + nt) * 32 + lane]);
#pragma unroll
            for (int t = 0; t < 2; t++) {
                mma_bf16(acc[t][nt], aH[t], bh.x, bh.y);
                mma_bf16(acc[t][nt], aL[t], bh.x, bh.y);
                mma_bf16(acc[t][nt], aH[t], bl.x, bl.y);
            }
        }
    }
#pragma unroll
    for (int t = 0; t < 2; t++)
#pragma unroll
        for (int nt = 0; nt < 8; nt++) {
            int n0 = nt * 8 + tig * 2;
#pragma unroll
            for (int h = 0; h < 2; h++) {
                int m = mm[t][h];
                int row = gy0 + (m >> 7), col = gx0 + (m & 127);
                if (row < W2F && col < W2F && n0 < 60) {
                    float v0 = acc[t][nt][h * 2]     + __ldg(&bias[n0]);
                    H2[(size_t)n0 * H2SZ + row * W2F + col] = f32_to_hl(fmaxf(v0, 0.f));
                    if (n0 + 1 < 60) {
                        float v1 = acc[t][nt][h * 2 + 1] + __ldg(&bias[n0 + 1]);
                        H2[(size_t)(n0 + 1) * H2SZ + row * W2F + col] = f32_to_hl(fmaxf(v1, 0.f));
                    }
                }
            }
        }
}

// ---------------- K3: deconv2 per-patch GEMM, K-split x M-split (4 CTAs/patch) ----------------
// smem u32: crop[25230] + zero zone to 25970 + kOff[768] = 26738 u32 = 106952 B
#define D2_SMEM 106952
__global__ void __launch_bounds__(320, 2)
deconv2_mma_kernel(const uint32_t* __restrict__ H2, const float* __restrict__ bias,
                   float* __restrict__ part) {
    extern __shared__ uint32_t s[];
    uint32_t* kOff = s + 25970;
    const int cta = blockIdx.x;
    const int n = cta >> 2, half = (cta >> 1) & 1, mhalf = cta & 1;
    const int gy0 = (n / NHH) * 16, gx0 = (n % NHH) * 16;
    const int tid = threadIdx.x, lane = tid & 31, wid = tid >> 5;
    const int gid = lane >> 2, tig = lane & 3;

    for (int i = tid; i < 25970; i += 320) s[i] = 0u;
    for (int k = tid; k < 768; k += 320) {
        uint32_t v = 25230u;
        if (k < 750) { int ci = k / 25, rr = k % 25; v = ci * 841 + (rr / 5) * 29 + (rr % 5); }
        kOff[k] = v;
    }
    __syncthreads();
    for (int i = tid; i < 13230; i += 320) {
        int ci = i / 441, rem = i % 441, y = rem / 21, x = rem % 21;
        s[ci * 841 + (y + 4) * 29 + (x + 4)] =
            H2[(size_t)(half * 30 + ci) * H2SZ + (gy0 + y) * W2F + (gx0 + x)];
    }
    int ro[2][2], mm[2][2];
#pragma unroll
    for (int t = 0; t < 2; t++)
#pragma unroll
        for (int h = 0; h < 2; h++) {
            int m = mhalf * 320 + wid * 32 + t * 16 + gid + h * 8;
            mm[t][h] = m;
            ro[t][h] = (m / 25) * 29 + (m % 25);
        }
    __syncthreads();

    float acc[2][3][4];
#pragma unroll
    for (int t = 0; t < 2; t++)
#pragma unroll
        for (int nt = 0; nt < 3; nt++)
#pragma unroll
            for (int j = 0; j < 4; j++) acc[t][nt][j] = 0.f;

    for (int kcl = 0; kcl < 48; kcl++) {
        int kb = kcl * 16 + 2 * tig;
        uint2 ko01 = *reinterpret_cast<const uint2*>(&kOff[kb]);
        uint2 ko89 = *reinterpret_cast<const uint2*>(&kOff[kb + 8]);
        uint32_t aH[2][4], aL[2][4];
#pragma unroll
        for (int t = 0; t < 2; t++) {
            uint32_t e00 = s[ko01.x + ro[t][0]], e01 = s[ko01.y + ro[t][0]];
            uint32_t e10 = s[ko01.x + ro[t][1]], e11 = s[ko01.y + ro[t][1]];
            uint32_t e08 = s[ko89.x + ro[t][0]], e09 = s[ko89.y + ro[t][0]];
            uint32_t e18 = s[ko89.x + ro[t][1]], e19 = s[ko89.y + ro[t][1]];
            aH[t][0] = __byte_perm(e00, e01, 0x5410); aL[t][0] = __byte_perm(e00, e01, 0x7632);
            aH[t][1] = __byte_perm(e10, e11, 0x5410); aL[t][1] = __byte_perm(e10, e11, 0x7632);
            aH[t][2] = __byte_perm(e08, e09, 0x5410); aL[t][2] = __byte_perm(e08, e09, 0x7632);
            aH[t][3] = __byte_perm(e18, e19, 0x5410); aL[t][3] = __byte_perm(e18, e19, 0x7632);
        }
#pragma unroll
        for (int nt = 0; nt < 3; nt++) {
            uint2 bh = __ldg(&g_Bd2H[((half * 48 + kcl) * 3 + nt) * 32 + lane]);
            uint2 bl = __ldg(&g_Bd2L[((half * 48 + kcl) * 3 + nt) * 32 + lane]);
#pragma unroll
            for (int t = 0; t < 2; t++) {
                mma_bf16(acc[t][nt], aH[t], bh.x, bh.y);
                mma_bf16(acc[t][nt], aL[t], bh.x, bh.y);
                mma_bf16(acc[t][nt], aH[t], bl.x, bl.y);
            }
        }
    }
    float* pb = part + ((size_t)half * NP + n) * 15000;
#pragma unroll
    for (int t = 0; t < 2; t++)
#pragma unroll
        for (int nt = 0; nt < 3; nt++) {
            int n0 = nt * 8 + tig * 2;   // 0..22
#pragma unroll
            for (int h = 0; h < 2; h++) {
                int m = mm[t][h];
                if (m < 625) {
                    float v0 = acc[t][nt][h * 2]     + (half ? 0.f : __ldg(&bias[n0]));
                    float v1 = acc[t][nt][h * 2 + 1] + (half ? 0.f : __ldg(&bias[n0 + 1]));
                    reinterpret_cast<float2*>(pb)[(n0 >> 1) * 625 + m] = make_float2(v0, v1);
                }
            }
        }
}

// ---------------- K4: reduce partials + ELU + deconv1 + einsum (FFMA2) ----------------
__global__ void __launch_bounds__(512, 1)
deconv1_p_kernel(const float* __restrict__ part, const float* __restrict__ w1,
                 const float* __restrict__ b1, const float* __restrict__ lin_w,
                 const float* __restrict__ lin_b, float* __restrict__ P) {
    extern __shared__ ull sm[];
    ull* sIn = sm;  // 12*1521
    float2* sWf = reinterpret_cast<float2*>(sm + 18252);
    const int n = blockIdx.x;
    const int bd = blockDim.x;
    const float lw0 = lin_w[2 * n], lw1 = lin_w[2 * n + 1];
    for (int i = threadIdx.x; i < 18252; i += bd) sIn[i] = 0ull;
    __syncthreads();
    const float2* p0 = reinterpret_cast<const float2*>(part + (size_t)n * 15000);
    const float2* p1 = reinterpret_cast<const float2*>(part + ((size_t)NP + n) * 15000);
    for (int i = threadIdx.x; i < 7500; i += bd) {
        int cp = i / 625, rem = i % 625;
        int y = rem / 25, x = rem % 25;
        float2 a = p0[i], b = p1[i];
        float vx = elu1(a.x + b.x), vy = elu1(a.y + b.y);
        sIn[cp * 1521 + (y + 7) * 39 + (x + 7)] =
            ((ull)__float_as_uint(vy) << 32) | (ull)__float_as_uint(vx);
    }
    for (int i = threadIdx.x; i < 768; i += bd) {
        int cp = i >> 6, rem = i & 63;
        int ky = rem >> 3, kx = rem & 7;
        int f0 = (2 * cp) * 128 + (7 - ky) * 8 + (7 - kx);
        int f1 = (2 * cp + 1) * 128 + (7 - ky) * 8 + (7 - kx);
        sWf[i] = make_float2(lw0 * w1[f0] + lw1 * w1[f0 + 64],
                             lw0 * w1[f1] + lw1 * w1[f1 + 64]);
    }
    __syncthreads();
    const ull* sW = reinterpret_cast<const ull*>(sWf);
    const float cst = (lw0 + lw1) * b1[0] + lin_b[n];
    const int t = threadIdx.x;
    const int y = t >> 4;
    const int x0 = (t & 15) * 2;
    ull acc0 = 0ull, acc1 = 0ull;
    for (int cp = 0; cp < 12; cp++) {
#pragma unroll
        for (int ky = 0; ky < 8; ky++) {
            ull reg[9];
            const ull* row = sIn + cp * 1521 + (y + ky) * 39 + x0;
#pragma unroll
            for (int i = 0; i < 9; i++) reg[i] = row[i];
            const ull* wr = sW + cp * 64 + ky * 8;
#pragma unroll
            for (int kx = 0; kx < 8; kx++) {
                ull wv = wr[kx];
                fma2(acc0, reg[kx], wv);
                fma2(acc1, reg[kx + 1], wv);
            }
        }
    }
    float* outp = P + (size_t)n * 1024 + y * 32 + x0;
    outp[0] = lo_f(acc0) + hi_f(acc0) + cst;
    outp[1] = lo_f(acc1) + hi_f(acc1) + cst;
}

// ---------------- K5: overlap-add + residual ----------------
__global__ void final_kernel(const float* __restrict__ x2, const float* __restrict__ P,
                             const float* __restrict__ linear1_w, float* __restrict__ out) {
    int idx = blockIdx.x * blockDim.x + threadIdx.x;
    if (idx >= HH * WW) return;
    int Y = idx >> 10, X = idx & 1023;
    float s = 0.f;
    int iy = Y >> 4, ix = X >> 4;
#pragma unroll
    for (int di = 0; di < 2; di++) {
        int i = iy - di;
        if (i < 0 || i > 62) continue;
        int py = Y - i * 16;
        if (py >= 32) continue;
#pragma unroll
        for (int dj = 0; dj < 2; dj++) {
            int j = ix - dj;
            if (j < 0 || j > 62) continue;
            int px = X - j * 16;
            if (px >= 32) continue;
            s += P[(size_t)(i * NHH + j) * 1024 + py * 32 + px];
        }
    }
    out[idx] = x2[idx] - s * linear1_w[0];
}

// ---------------------------------------------------------------------------
extern "C" void kernel_launch(void* const* d_in, const int* in_sizes, int n_in,
                              void* d_out, int out_size) {
    const float* x1        = (const float*)d_in[0];
    const float* x2        = (const float*)d_in[1];
    const float* conv1_w   = (const float*)d_in[2];
    const float* conv1_b   = (const float*)d_in[3];
    const float* conv2_w   = (const float*)d_in[4];
    const float* conv2_b   = (const float*)d_in[5];
    const float* deconv2_w = (const float*)d_in[6];
    const float* deconv2_b = (const float*)d_in[7];
    const float* deconv1_w = (const float*)d_in[8];
    const float* deconv1_b = (const float*)d_in[9];
    const float* lin_w     = (const float*)d_in[10];
    const float* lin_b     = (const float*)d_in[11];
    const float* linear1_w = (const float*)d_in[12];
    float* out = (float*)d_out;

    uint32_t *H1, *H2;
    float *part, *P;
    cudaGetSymbolAddress((void**)&H1,   g_H1);
    cudaGetSymbolAddress((void**)&H2,   g_H2);
    cudaGetSymbolAddress((void**)&part, g_part);
    cudaGetSymbolAddress((void**)&P,    g_p);

    const int smem4 = (18252 + 768) * 8;
    cudaFuncSetAttribute(conv2_full_kernel,  cudaFuncAttributeMaxDynamicSharedMemorySize, C2_SMEM);
    cudaFuncSetAttribute(deconv2_mma_kernel, cudaFuncAttributeMaxDynamicSharedMemorySize, D2_SMEM);
    cudaFuncSetAttribute(deconv1_p_kernel,   cudaFuncAttributeMaxDynamicSharedMemorySize, smem4);

    pack_kernel<<<(10240 + 9216 + 255) / 256, 256>>>(conv2_w, deconv2_w);
    conv1_full_kernel<<<dim3(16, 64), 256>>>(x1, x2, conv1_w, conv1_b, H1);
    conv2_full_kernel<<<507 * 8, 256, C2_SMEM>>>(H1, conv2_b, H2);
    deconv2_mma_kernel<<<NP * 4, 320, D2_SMEM>>>(H2, deconv2_b, part);
    deconv1_p_kernel<<<NP, 512, smem4>>>(part, deconv1_w, deconv1_b, lin_w, lin_b, P);
    final_kernel<<<(HH * WW + 255) / 256, 256>>>(x2, P, linear1_w, out);
}

// round 11
// speedup vs baseline: 3.1707x; 1.1709x over previous
#include <cuda_runtime.h>
#include <cuda_bf16.h>
#include <math.h>
#include <stdint.h>

#define HH 1024
#define WW 1024
#define NHH 63
#define NP 3969
#define W1F 1017
#define W2F 1013
#define H1SZ (W1F * W1F)
#define H2SZ (W2F * W2F)

typedef unsigned long long ull;

// -------- global intermediates --------
__device__ uint32_t g_H1hi[(size_t)12 * H1SZ];   // channel-pair bf16 hi planes
__device__ uint32_t g_H1lo[(size_t)12 * H1SZ];
__device__ uint32_t g_H2hi[(size_t)30 * H2SZ];
__device__ uint32_t g_H2lo[(size_t)30 * H2SZ];
__device__ float    g_part[(size_t)2 * NP * 15000];
__device__ float    g_p[(size_t)NP * 1024];
__device__ uint4    g_Bc[40 * 8 * 32];           // conv2 B frags (hi0,hi1,lo0,lo1)
__device__ uint4    g_Bd[2 * 48 * 3 * 32];       // deconv2 B frags

__device__ __forceinline__ float elu1(float v) { return v > 0.f ? v : expm1f(v); }
__device__ __forceinline__ uint32_t bfpack(float a, float b) {
    return (uint32_t)__bfloat16_as_ushort(__float2bfloat16(a)) |
           ((uint32_t)__bfloat16_as_ushort(__float2bfloat16(b)) << 16);
}
__device__ __forceinline__ void hlpack(float v0, float v1, uint32_t &hi, uint32_t &lo) {
    __nv_bfloat16 h0 = __float2bfloat16(v0), h1 = __float2bfloat16(v1);
    hi = (uint32_t)__bfloat16_as_ushort(h0) | ((uint32_t)__bfloat16_as_ushort(h1) << 16);
    lo = bfpack(v0 - __bfloat162float(h0), v1 - __bfloat162float(h1));
}
__device__ __forceinline__ void fma2(ull &d, ull a, ull b) {
    asm("fma.rn.f32x2 %0, %1, %2, %0;" : "+l"(d) : "l"(a), "l"(b));
}
__device__ __forceinline__ float lo_f(ull u) { return __uint_as_float((unsigned)u); }
__device__ __forceinline__ float hi_f(ull u) { return __uint_as_float((unsigned)(u >> 32)); }

__device__ __forceinline__ void mma_bf16(float d[4], const uint32_t a[4],
                                         uint32_t b0, uint32_t b1) {
    asm("mma.sync.aligned.m16n8k16.row.col.f32.bf16.bf16.f32 "
        "{%0,%1,%2,%3}, {%4,%5,%6,%7}, {%8,%9}, {%0,%1,%2,%3};"
        : "+f"(d[0]), "+f"(d[1]), "+f"(d[2]), "+f"(d[3])
        : "r"(a[0]), "r"(a[1]), "r"(a[2]), "r"(a[3]), "r"(b0), "r"(b1));
}

// ---------------- K0: pack B frag tables (k-order = tap*nc + ci) ----------------
__global__ void pack_kernel(const float* __restrict__ w2, const float* __restrict__ wd2) {
    int j = blockIdx.x * blockDim.x + threadIdx.x;
    if (j < 10240) {
        // conv2: idx=(kcl*8+nt)*32+lane; k = tap*24+ci, K=600 pad 640
        int lane = j & 31, nt = (j >> 5) & 7, kcl = j >> 8;
        int gid = lane >> 2, tig = lane & 3;
        int n = nt * 8 + gid;
        uint32_t w4[4];
#pragma unroll
        for (int s = 0; s < 2; s++) {
            int k = kcl * 16 + 2 * tig + s * 8;
            float v0 = 0.f, v1 = 0.f;
            if (n < 60 && k < 600) {
                int tap = k / 24, ci = k % 24;
                v0 = w2[n * 600 + ci * 25 + tap];
                v1 = w2[n * 600 + (ci + 1) * 25 + tap];
            }
            hlpack(v0, v1, w4[s], w4[2 + s]);
        }
        g_Bc[j] = make_uint4(w4[0], w4[1], w4[2], w4[3]);
    } else if (j < 10240 + 9216) {
        // deconv2: idx=((half*48+kcl)*3+nt)*32+lane; k = tap*30+cil, K=750 pad 768
        int i = j - 10240;
        int lane = i & 31, nt = (i >> 5) % 3, kcl = (i / 96) % 48, half = i / 4608;
        int gid = lane >> 2, tig = lane & 3;
        int r = nt * 8 + gid;
        uint32_t w4[4];
#pragma unroll
        for (int s = 0; s < 2; s++) {
            int k = kcl * 16 + 2 * tig + s * 8;
            float v0 = 0.f, v1 = 0.f;
            if (k < 750) {
                int tap = k / 30, cil = k % 30, ci = half * 30 + cil;
                v0 = wd2[ci * 600 + r * 25 + (24 - tap)];
                v1 = wd2[(ci + 1) * 600 + r * 25 + (24 - tap)];
            }
            hlpack(v0, v1, w4[s], w4[2 + s]);
        }
        g_Bd[i] = make_uint4(w4[0], w4[1], w4[2], w4[3]);
    }
}

// ---------------- K1: conv1 full-image (FFMA2) -> channel-pair hi/lo planes ----------------
__global__ void __launch_bounds__(256)
conv1_full_kernel(const float* __restrict__ x1, const float* __restrict__ x2,
                  const float* __restrict__ w, const float* __restrict__ b,
                  uint32_t* __restrict__ H1hi, uint32_t* __restrict__ H1lo) {
    __shared__ float2 sImg[23 * 72];
    __shared__ float2 sW2[24 * 64];
    __shared__ float sB[24];
    const int gy0 = blockIdx.y * 16, gx0 = blockIdx.x * 64;
    const int tid = threadIdx.x;
    for (int i = tid; i < 23 * 72; i += 256) {
        int r = i / 72, c = i % 72;
        int gy = gy0 + r, gx = gx0 + c;
        float2 v = make_float2(0.f, 0.f);
        if (c < 71 && gy < 1024 && gx < 1024) {
            int g = gy * 1024 + gx;
            v = make_float2(x1[g], x2[g]);
        }
        sImg[i] = v;
    }
    for (int i = tid; i < 1536; i += 256) {
        int c = i >> 6, rem = i & 63;
        sW2[i] = make_float2(w[c * 128 + rem], w[c * 128 + 64 + rem]);
    }
    if (tid < 24) sB[tid] = b[tid];
    __syncthreads();
    const ull* sP = reinterpret_cast<const ull*>(sImg);
    const ull* sW = reinterpret_cast<const ull*>(sW2);
    const int y = tid >> 4, x0 = (tid & 15) * 4;
    const int gy = gy0 + y;
    for (int c0 = 0; c0 < 24; c0 += 4) {
        ull acc[4][4];
#pragma unroll
        for (int cc = 0; cc < 4; cc++)
#pragma unroll
            for (int j = 0; j < 4; j++) acc[cc][j] = 0ull;
#pragma unroll
        for (int ky = 0; ky < 8; ky++) {
            ull reg[11];
            const ull* row = sP + (y + ky) * 72 + x0;
#pragma unroll
            for (int i = 0; i < 11; i++) reg[i] = row[i];
#pragma unroll
            for (int cc = 0; cc < 4; cc++) {
                const ull* wr = sW + (c0 + cc) * 64 + ky * 8;
#pragma unroll
                for (int kx = 0; kx < 8; kx++) {
                    ull wv = wr[kx];
#pragma unroll
                    for (int j = 0; j < 4; j++) fma2(acc[cc][j], reg[j + kx], wv);
                }
            }
        }
        if (gy < W1F) {
#pragma unroll
            for (int pp = 0; pp < 2; pp++) {
                int cp = (c0 >> 1) + pp;
                float b0 = sB[c0 + 2 * pp], b1 = sB[c0 + 2 * pp + 1];
#pragma unroll
                for (int j = 0; j < 4; j++) {
                    int gx = gx0 + x0 + j;
                    if (gx < W1F) {
                        float v0 = elu1(lo_f(acc[2 * pp][j]) + hi_f(acc[2 * pp][j]) + b0);
                        float v1 = elu1(lo_f(acc[2 * pp + 1][j]) + hi_f(acc[2 * pp + 1][j]) + b1);
                        uint32_t hi, lo;
                        hlpack(v0, v1, hi, lo);
                        size_t pix = (size_t)cp * H1SZ + gy * W1F + gx;
                        H1hi[pix] = hi;
                        H1lo[pix] = lo;
                    }
                }
            }
        }
    }
}

// ---------------- K2: conv2 full-image GEMM -> H2 hi/lo planes ----------------
// 8 warps x 32 rows each (R8 layout); each warp does all 8 n-tiles.
// smem u32: sHi[9768] sLo[9768] kOff[320] = 19856 u32 = 79424 B
#define C2_PS 9768
#define C2_SMEM 79424
__global__ void __launch_bounds__(256, 2)
conv2_full_kernel(const uint32_t* __restrict__ H1hi, const uint32_t* __restrict__ H1lo,
                  const float* __restrict__ bias,
                  uint32_t* __restrict__ H2hi, uint32_t* __restrict__ H2lo) {
    extern __shared__ uint32_t s[];
    uint32_t* sLo = s + C2_PS;
    uint32_t* kOff = s + 2 * C2_PS;
    const int bid = blockIdx.x;
    const int gy0 = (bid >> 3) * 2, gx0 = (bid & 7) * 128;
    const int tid = threadIdx.x, lane = tid & 31, wid = tid >> 5;
    const int gid = lane >> 2, tig = lane & 3;

    for (int i = tid; i < C2_PS; i += 256) {
        uint32_t vh = 0u, vl = 0u;
        if (i < 9504) {
            int cp = i / 792, rem = i % 792, r = rem / 132, c = rem % 132;
            int gy = gy0 + r, gx = gx0 + c;
            if (gy < W1F && gx < W1F) {
                size_t g = (size_t)cp * H1SZ + gy * W1F + gx;
                vh = H1hi[g]; vl = H1lo[g];
            }
        }
        s[i] = vh; sLo[i] = vl;
    }
    for (int p = tid; p < 320; p += 256) {
        int k = 2 * p;
        uint32_t v = 9504u;
        if (k < 600) { int tap = k / 24, cp = (k % 24) >> 1;
                       v = cp * 792 + (tap / 5) * 132 + (tap % 5); }
        kOff[p] = v;
    }
    int ro[2][2], mm[2][2];
#pragma unroll
    for (int t = 0; t < 2; t++)
#pragma unroll
        for (int h = 0; h < 2; h++) {
            int m = wid * 32 + t * 16 + gid + h * 8;
            mm[t][h] = m;
            ro[t][h] = (m >> 7) * 132 + (m & 127);
        }
    __syncthreads();

    float acc[2][8][4];
#pragma unroll
    for (int t = 0; t < 2; t++)
#pragma unroll
        for (int nt = 0; nt < 8; nt++)
#pragma unroll
            for (int j = 0; j < 4; j++) acc[t][nt][j] = 0.f;

    for (int kcl = 0; kcl < 40; kcl++) {
        uint32_t ko0 = kOff[kcl * 8 + tig], ko1 = kOff[kcl * 8 + tig + 4];
        uint32_t aH[2][4], aL[2][4];
#pragma unroll
        for (int t = 0; t < 2; t++) {
            aH[t][0] = s[ko0 + ro[t][0]];  aL[t][0] = sLo[ko0 + ro[t][0]];
            aH[t][1] = s[ko0 + ro[t][1]];  aL[t][1] = sLo[ko0 + ro[t][1]];
            aH[t][2] = s[ko1 + ro[t][0]];  aL[t][2] = sLo[ko1 + ro[t][0]];
            aH[t][3] = s[ko1 + ro[t][1]];  aL[t][3] = sLo[ko1 + ro[t][1]];
        }
#pragma unroll
        for (int nt = 0; nt < 8; nt++) {
            uint4 bd = __ldg(&g_Bc[(kcl * 8 + nt) * 32 + lane]);
#pragma unroll
            for (int t = 0; t < 2; t++) {
                mma_bf16(acc[t][nt], aH[t], bd.x, bd.y);
                mma_bf16(acc[t][nt], aL[t], bd.x, bd.y);
                mma_bf16(acc[t][nt], aH[t], bd.z, bd.w);
            }
        }
    }
#pragma unroll
    for (int t = 0; t < 2; t++)
#pragma unroll
        for (int nt = 0; nt < 8; nt++) {
            int n0 = nt * 8 + tig * 2;
            int cp = n0 >> 1;
#pragma unroll
            for (int h = 0; h < 2; h++) {
                int m = mm[t][h];
                int row = gy0 + (m >> 7), col = gx0 + (m & 127);
                if (row < W2F && col < W2F && n0 < 60) {
                    float v0 = acc[t][nt][h * 2]     + __ldg(&bias[n0]);
                    float v1 = acc[t][nt][h * 2 + 1] + __ldg(&bias[n0 + 1]);
                    uint32_t hi, lo;
                    hlpack(fmaxf(v0, 0.f), fmaxf(v1, 0.f), hi, lo);
                    size_t pix = (size_t)cp * H2SZ + row * W2F + col;
                    H2hi[pix] = hi;
                    H2lo[pix] = lo;
                }
            }
        }
}

// ---------------- K3: deconv2 per-patch GEMM, K-split x M-split, windowed staging ----------------
// smem u32: sHi[7800] sLo[7800] kOff[384] = 15984 u32 = 63936 B
#define D2_PS 7800
#define D2_SMEM 63936
__global__ void __launch_bounds__(320, 2)
deconv2_mma_kernel(const uint32_t* __restrict__ H2hi, const uint32_t* __restrict__ H2lo,
                   const float* __restrict__ bias, float* __restrict__ part) {
    extern __shared__ uint32_t s[];
    uint32_t* sLo = s + D2_PS;
    uint32_t* kOff = s + 2 * D2_PS;
    const int cta = blockIdx.x;
    const int n = cta >> 2, half = (cta >> 1) & 1, mhalf = cta & 1;
    const int gy0 = (n / NHH) * 16, gx0 = (n % NHH) * 16;
    const int tid = threadIdx.x, lane = tid & 31, wid = tid >> 5;
    const int gid = lane >> 2, tig = lane & 3;

    for (int i = tid; i < 2 * D2_PS; i += 320) s[i] = 0u;
    for (int p = tid; p < 384; p += 320) {
        int k = 2 * p;
        uint32_t v = 7395u;
        if (k < 750) { int tap = k / 30, cp = (k % 30) >> 1;
                       v = cp * 493 + (tap / 5) * 29 + (tap % 5); }
        kOff[p] = v;
    }
    __syncthreads();
    // stage 13-row data window: mhalf0 -> patch y 0..12 at l=y+4; mhalf1 -> patch y 8..20 at l=y-8
    for (int i = tid; i < 15 * 13 * 21; i += 320) {
        int cp = i / 273, rem = i % 273, lr = rem / 21, c = rem % 21;
        int l = lr + (mhalf ? 0 : 4);
        int y = l + mhalf * 12 - 4;          // patch y (0..20)
        size_t g = (size_t)(half * 15 + cp) * H2SZ + (gy0 + y) * W2F + (gx0 + c);
        int off = cp * 493 + l * 29 + (c + 4);
        s[off] = H2hi[g];
        sLo[off] = H2lo[g];
    }
    int ro[2][2], mm[2][2];
#pragma unroll
    for (int t = 0; t < 2; t++)
#pragma unroll
        for (int h = 0; h < 2; h++) {
            int m = mhalf * 320 + wid * 32 + t * 16 + gid + h * 8;
            mm[t][h] = m;
            ro[t][h] = (m / 25 - mhalf * 12) * 29 + (m % 25);
        }
    __syncthreads();

    float acc[2][3][4];
#pragma unroll
    for (int t = 0; t < 2; t++)
#pragma unroll
        for (int nt = 0; nt < 3; nt++)
#pragma unroll
            for (int j = 0; j < 4; j++) acc[t][nt][j] = 0.f;

    for (int kcl = 0; kcl < 48; kcl++) {
        uint32_t ko0 = kOff[kcl * 8 + tig], ko1 = kOff[kcl * 8 + tig + 4];
        uint32_t aH[2][4], aL[2][4];
#pragma unroll
        for (int t = 0; t < 2; t++) {
            aH[t][0] = s[ko0 + ro[t][0]];  aL[t][0] = sLo[ko0 + ro[t][0]];
            aH[t][1] = s[ko0 + ro[t][1]];  aL[t][1] = sLo[ko0 + ro[t][1]];
            aH[t][2] = s[ko1 + ro[t][0]];  aL[t][2] = sLo[ko1 + ro[t][0]];
            aH[t][3] = s[ko1 + ro[t][1]];  aL[t][3] = sLo[ko1 + ro[t][1]];
        }
#pragma unroll
        for (int nt = 0; nt < 3; nt++) {
            uint4 bd = __ldg(&g_Bd[((half * 48 + kcl) * 3 + nt) * 32 + lane]);
#pragma unroll
            for (int t = 0; t < 2; t++) {
                mma_bf16(acc[t][nt], aH[t], bd.x, bd.y);
                mma_bf16(acc[t][nt], aL[t], bd.x, bd.y);
                mma_bf16(acc[t][nt], aH[t], bd.z, bd.w);
            }
        }
    }
    float* pb = part + ((size_t)half * NP + n) * 15000;
#pragma unroll
    for (int t = 0; t < 2; t++)
#pragma unroll
        for (int nt = 0; nt < 3; nt++) {
            int n0 = nt * 8 + tig * 2;   // 0..22
#pragma unroll
            for (int h = 0; h < 2; h++) {
                int m = mm[t][h];
                if (m < 625) {
                    float v0 = acc[t][nt][h * 2]     + (half ? 0.f : __ldg(&bias[n0]));
                    float v1 = acc[t][nt][h * 2 + 1] + (half ? 0.f : __ldg(&bias[n0 + 1]));
                    reinterpret_cast<float2*>(pb)[(n0 >> 1) * 625 + m] = make_float2(v0, v1);
                }
            }
        }
}

// ---------------- K4: reduce partials + ELU + deconv1 + einsum (FFMA2), y-split occ2 ----------------
// smem: sIn 12*897 ull + sWf 768 float2 = 92256 B
#define K4_SMEM 92256
__global__ void __launch_bounds__(256, 2)
deconv1_p_kernel(const float* __restrict__ part, const float* __restrict__ w1,
                 const float* __restrict__ b1, const float* __restrict__ lin_w,
                 const float* __restrict__ lin_b, float* __restrict__ P) {
    extern __shared__ ull sm[];
    ull* sIn = sm;  // 12*897 = 10764
    float2* sWf = reinterpret_cast<float2*>(sm + 10764);
    const int bid = blockIdx.x;
    const int n = bid >> 1, half = bid & 1;
    const float lw0 = lin_w[2 * n], lw1 = lin_w[2 * n + 1];
    for (int i = threadIdx.x; i < 10764; i += 256) sIn[i] = 0ull;
    __syncthreads();
    const float2* p0 = reinterpret_cast<const float2*>(part + (size_t)n * 15000);
    const float2* p1 = reinterpret_cast<const float2*>(part + ((size_t)NP + n) * 15000);
    // 16 data rows per half: half0 img y 0..15 at l=y+7, half1 img y 9..24 at l=y-9
    for (int i = threadIdx.x; i < 12 * 16 * 25; i += 256) {
        int cp = i / 400, rem = i % 400, lr = rem / 25, x = rem % 25;
        int img_y = lr + (half ? 9 : 0);
        int l = img_y + 7 - half * 16;
        float2 a = p0[cp * 625 + img_y * 25 + x], b = p1[cp * 625 + img_y * 25 + x];
        float vx = elu1(a.x + b.x), vy = elu1(a.y + b.y);
        sIn[cp * 897 + l * 39 + x + 7] =
            ((ull)__float_as_uint(vy) << 32) | (ull)__float_as_uint(vx);
    }
    for (int i = threadIdx.x; i < 768; i += 256) {
        int cp = i >> 6, rem = i & 63;
        int ky = rem >> 3, kx = rem & 7;
        int f0 = (2 * cp) * 128 + (7 - ky) * 8 + (7 - kx);
        int f1 = (2 * cp + 1) * 128 + (7 - ky) * 8 + (7 - kx);
        sWf[i] = make_float2(lw0 * w1[f0] + lw1 * w1[f0 + 64],
                             lw0 * w1[f1] + lw1 * w1[f1 + 64]);
    }
    __syncthreads();
    const ull* sW = reinterpret_cast<const ull*>(sWf);
    const float cst = (lw0 + lw1) * b1[0] + lin_b[n];
    const int t = threadIdx.x;
    const int yl = t >> 4;            // 0..15
    const int x0 = (t & 15) * 2;
    ull acc0 = 0ull, acc1 = 0ull;
    for (int cp = 0; cp < 12; cp++) {
#pragma unroll
        for (int ky = 0; ky < 8; ky++) {
            ull reg[9];
            const ull* row = sIn + cp * 897 + (yl + ky) * 39 + x0;
#pragma unroll
            for (int i = 0; i < 9; i++) reg[i] = row[i];
            const ull* wr = sW + cp * 64 + ky * 8;
#pragma unroll
            for (int kx = 0; kx < 8; kx++) {
                ull wv = wr[kx];
                fma2(acc0, reg[kx], wv);
                fma2(acc1, reg[kx + 1], wv);
            }
        }
    }
    float* outp = P + (size_t)n * 1024 + (half * 16 + yl) * 32 + x0;
    outp[0] = lo_f(acc0) + hi_f(acc0) + cst;
    outp[1] = lo_f(acc1) + hi_f(acc1) + cst;
}

// ---------------- K5: overlap-add + residual ----------------
__global__ void final_kernel(const float* __restrict__ x2, const float* __restrict__ P,
                             const float* __restrict__ linear1_w, float* __restrict__ out) {
    int idx = blockIdx.x * blockDim.x + threadIdx.x;
    if (idx >= HH * WW) return;
    int Y = idx >> 10, X = idx & 1023;
    float s = 0.f;
    int iy = Y >> 4, ix = X >> 4;
#pragma unroll
    for (int di = 0; di < 2; di++) {
        int i = iy - di;
        if (i < 0 || i > 62) continue;
        int py = Y - i * 16;
        if (py >= 32) continue;
#pragma unroll
        for (int dj = 0; dj < 2; dj++) {
            int j = ix - dj;
            if (j < 0 || j > 62) continue;
            int px = X - j * 16;
            if (px >= 32) continue;
            s += P[(size_t)(i * NHH + j) * 1024 + py * 32 + px];
        }
    }
    out[idx] = x2[idx] - s * linear1_w[0];
}

// ---------------------------------------------------------------------------
extern "C" void kernel_launch(void* const* d_in, const int* in_sizes, int n_in,
                              void* d_out, int out_size) {
    const float* x1        = (const float*)d_in[0];
    const float* x2        = (const float*)d_in[1];
    const float* conv1_w   = (const float*)d_in[2];
    const float* conv1_b   = (const float*)d_in[3];
    const float* conv2_w   = (const float*)d_in[4];
    const float* conv2_b   = (const float*)d_in[5];
    const float* deconv2_w = (const float*)d_in[6];
    const float* deconv2_b = (const float*)d_in[7];
    const float* deconv1_w = (const float*)d_in[8];
    const float* deconv1_b = (const float*)d_in[9];
    const float* lin_w     = (const float*)d_in[10];
    const float* lin_b     = (const float*)d_in[11];
    const float* linear1_w = (const float*)d_in[12];
    float* out = (float*)d_out;

    uint32_t *H1hi, *H1lo, *H2hi, *H2lo;
    float *part, *P;
    cudaGetSymbolAddress((void**)&H1hi, g_H1hi);
    cudaGetSymbolAddress((void**)&H1lo, g_H1lo);
    cudaGetSymbolAddress((void**)&H2hi, g_H2hi);
    cudaGetSymbolAddress((void**)&H2lo, g_H2lo);
    cudaGetSymbolAddress((void**)&part, g_part);
    cudaGetSymbolAddress((void**)&P,    g_p);

    cudaFuncSetAttribute(conv2_full_kernel,  cudaFuncAttributeMaxDynamicSharedMemorySize, C2_SMEM);
    cudaFuncSetAttribute(deconv2_mma_kernel, cudaFuncAttributeMaxDynamicSharedMemorySize, D2_SMEM);
    cudaFuncSetAttribute(deconv1_p_kernel,   cudaFuncAttributeMaxDynamicSharedMemorySize, K4_SMEM);

    pack_kernel<<<(10240 + 9216 + 255) / 256, 256>>>(conv2_w, deconv2_w);
    conv1_full_kernel<<<dim3(16, 64), 256>>>(x1, x2, conv1_w, conv1_b, H1hi, H1lo);
    conv2_full_kernel<<<507 * 8, 256, C2_SMEM>>>(H1hi, H1lo, conv2_b, H2hi, H2lo);
    deconv2_mma_kernel<<<NP * 4, 320, D2_SMEM>>>(H2hi, H2lo, deconv2_b, part);
    deconv1_p_kernel<<<NP * 2, 256, K4_SMEM>>>(part, deconv1_w, deconv1_b, lin_w, lin_b, P);
    final_kernel<<<(HH * WW + 255) / 256, 256>>>(x2, P, linear1_w, out);
}

// round 14
// speedup vs baseline: 3.4055x; 1.0741x over previous
#include <cuda_runtime.h>
#include <cuda_fp16.h>
#include <math.h>
#include <stdint.h>

#define HH 1024
#define WW 1024
#define NHH 63
#define NP 3969
#define W1F 1017
#define W2F 1013
#define H1SZ (W1F * W1F)
#define H2SZ (W2F * W2F)

typedef unsigned long long ull;

// -------- global intermediates --------
// interleaved channel-pair fp16 planes: u64 = hiPair | loPair<<32
__device__ ull      g_H1[(size_t)12 * H1SZ];
__device__ ull      g_H2[(size_t)30 * H2SZ];
__device__ float    g_part[(size_t)2 * NP * 15000];
__device__ float    g_p[(size_t)NP * 1024];
__device__ uint2    g_Bc[40 * 8 * 32];           // conv2 B frags (fp16 hi only)
__device__ uint2    g_Bd[2 * 48 * 3 * 32];       // deconv2 B frags

__device__ __forceinline__ float elu1(float v) { return v > 0.f ? v : expm1f(v); }
__device__ __forceinline__ uint32_t hpack(float a, float b) {
    return (uint32_t)__half_as_ushort(__float2half(a)) |
           ((uint32_t)__half_as_ushort(__float2half(b)) << 16);
}
// pack two fp32 values into interleaved u64: low32 = hi fp16 pair, high32 = lo fp16 pair
__device__ __forceinline__ ull hl64(float v0, float v1) {
    __half h0 = __float2half(v0), h1 = __float2half(v1);
    uint32_t hi = (uint32_t)__half_as_ushort(h0) | ((uint32_t)__half_as_ushort(h1) << 16);
    uint32_t lo = hpack(v0 - __half2float(h0), v1 - __half2float(h1));
    return (ull)hi | ((ull)lo << 32);
}
__device__ __forceinline__ void fma2(ull &d, ull a, ull b) {
    asm("fma.rn.f32x2 %0, %1, %2, %0;" : "+l"(d) : "l"(a), "l"(b));
}
__device__ __forceinline__ float lo_f(ull u) { return __uint_as_float((unsigned)u); }
__device__ __forceinline__ float hi_f(ull u) { return __uint_as_float((unsigned)(u >> 32)); }

__device__ __forceinline__ void mma_f16(float d[4], const uint32_t a[4],
                                        uint32_t b0, uint32_t b1) {
    asm("mma.sync.aligned.m16n8k16.row.col.f32.f16.f16.f32 "
        "{%0,%1,%2,%3}, {%4,%5,%6,%7}, {%8,%9}, {%0,%1,%2,%3};"
        : "+f"(d[0]), "+f"(d[1]), "+f"(d[2]), "+f"(d[3])
        : "r"(a[0]), "r"(a[1]), "r"(a[2]), "r"(a[3]), "r"(b0), "r"(b1));
}

// ---------------- K0: pack B frag tables (fp16, k-order = tap*nc + ci) ----------------
__global__ void pack_kernel(const float* __restrict__ w2, const float* __restrict__ wd2) {
    int j = blockIdx.x * blockDim.x + threadIdx.x;
    if (j < 10240) {
        int lane = j & 31, nt = (j >> 5) & 7, kcl = j >> 8;
        int gid = lane >> 2, tig = lane & 3;
        int n = nt * 8 + gid;
        uint32_t fr[2];
#pragma unroll
        for (int s = 0; s < 2; s++) {
            int k = kcl * 16 + 2 * tig + s * 8;
            float v0 = 0.f, v1 = 0.f;
            if (n < 60 && k < 600) {
                int tap = k / 24, ci = k % 24;
                v0 = w2[n * 600 + ci * 25 + tap];
                v1 = w2[n * 600 + (ci + 1) * 25 + tap];
            }
            fr[s] = hpack(v0, v1);
        }
        g_Bc[j] = make_uint2(fr[0], fr[1]);
    } else if (j < 10240 + 9216) {
        int i = j - 10240;
        int lane = i & 31, nt = (i >> 5) % 3, kcl = (i / 96) % 48, half = i / 4608;
        int gid = lane >> 2, tig = lane & 3;
        int r = nt * 8 + gid;
        uint32_t fr[2];
#pragma unroll
        for (int s = 0; s < 2; s++) {
            int k = kcl * 16 + 2 * tig + s * 8;
            float v0 = 0.f, v1 = 0.f;
            if (k < 750) {
                int tap = k / 30, cil = k % 30, ci = half * 30 + cil;
                v0 = wd2[ci * 600 + r * 25 + (24 - tap)];
                v1 = wd2[(ci + 1) * 600 + r * 25 + (24 - tap)];
            }
            fr[s] = hpack(v0, v1);
        }
        g_Bd[i] = make_uint2(fr[0], fr[1]);
    }
}

// ---------------- K1: conv1 full-image (FFMA2) -> interleaved fp16 planes ----------------
__global__ void __launch_bounds__(256)
conv1_full_kernel(const float* __restrict__ x1, const float* __restrict__ x2,
                  const float* __restrict__ w, const float* __restrict__ b,
                  ull* __restrict__ H1) {
    __shared__ float2 sImg[23 * 72];
    __shared__ float2 sW2[24 * 64];
    __shared__ float sB[24];
    const int gy0 = blockIdx.y * 16, gx0 = blockIdx.x * 64;
    const int tid = threadIdx.x;
    for (int i = tid; i < 23 * 72; i += 256) {
        int r = i / 72, c = i % 72;
        int gy = gy0 + r, gx = gx0 + c;
        float2 v = make_float2(0.f, 0.f);
        if (c < 71 && gy < 1024 && gx < 1024) {
            int g = gy * 1024 + gx;
            v = make_float2(x1[g], x2[g]);
        }
        sImg[i] = v;
    }
    for (int i = tid; i < 1536; i += 256) {
        int c = i >> 6, rem = i & 63;
        sW2[i] = make_float2(w[c * 128 + rem], w[c * 128 + 64 + rem]);
    }
    if (tid < 24) sB[tid] = b[tid];
    __syncthreads();
    const ull* sP = reinterpret_cast<const ull*>(sImg);
    const ull* sW = reinterpret_cast<const ull*>(sW2);
    const int y = tid >> 4, x0 = (tid & 15) * 4;
    const int gy = gy0 + y;
    for (int c0 = 0; c0 < 24; c0 += 4) {
        ull acc[4][4];
#pragma unroll
        for (int cc = 0; cc < 4; cc++)
#pragma unroll
            for (int j = 0; j < 4; j++) acc[cc][j] = 0ull;
#pragma unroll
        for (int ky = 0; ky < 8; ky++) {
            ull reg[11];
            const ull* row = sP + (y + ky) * 72 + x0;
#pragma unroll
            for (int i = 0; i < 11; i++) reg[i] = row[i];
#pragma unroll
            for (int cc = 0; cc < 4; cc++) {
                const ull* wr = sW + (c0 + cc) * 64 + ky * 8;
#pragma unroll
                for (int kx = 0; kx < 8; kx++) {
                    ull wv = wr[kx];
#pragma unroll
                    for (int j = 0; j < 4; j++) fma2(acc[cc][j], reg[j + kx], wv);
                }
            }
        }
        if (gy < W1F) {
#pragma unroll
            for (int pp = 0; pp < 2; pp++) {
                int cp = (c0 >> 1) + pp;
                float b0 = sB[c0 + 2 * pp], b1 = sB[c0 + 2 * pp + 1];
#pragma unroll
                for (int j = 0; j < 4; j++) {
                    int gx = gx0 + x0 + j;
                    if (gx < W1F) {
                        float v0 = elu1(lo_f(acc[2 * pp][j]) + hi_f(acc[2 * pp][j]) + b0);
                        float v1 = elu1(lo_f(acc[2 * pp + 1][j]) + hi_f(acc[2 * pp + 1][j]) + b1);
                        H1[(size_t)cp * H1SZ + gy * W1F + gx] = hl64(v0, v1);
                    }
                }
            }
        }
    }
}

// ---------------- K2: conv2 full-image GEMM (fp16 2-term) -> H2 ----------------
// smem: s64[9768] u64 + kOff[320] u32 = 79424 B
#define C2_PS 9768
#define C2_SMEM (C2_PS * 8 + 320 * 4)
__global__ void __launch_bounds__(256, 2)
conv2_full_kernel(const ull* __restrict__ H1, const float* __restrict__ bias,
                  ull* __restrict__ H2) {
    extern __shared__ ull s64[];
    uint32_t* kOff = (uint32_t*)(s64 + C2_PS);
    const int bid = blockIdx.x;
    const int gy0 = (bid >> 3) * 2, gx0 = (bid & 7) * 128;
    const int tid = threadIdx.x, lane = tid & 31, wid = tid >> 5;
    const int gid = lane >> 2, tig = lane & 3;

    for (int i = tid; i < C2_PS; i += 256) {
        ull v = 0ull;
        if (i < 9504) {
            int cp = i / 792, rem = i % 792, r = rem / 132, c = rem % 132;
            int gy = gy0 + r, gx = gx0 + c;
            if (gy < W1F && gx < W1F) v = H1[(size_t)cp * H1SZ + gy * W1F + gx];
        }
        s64[i] = v;
    }
    for (int p = tid; p < 320; p += 256) {
        int k = 2 * p;
        uint32_t v = 9504u;
        if (k < 600) { int tap = k / 24, cp = (k % 24) >> 1;
                       v = cp * 792 + (tap / 5) * 132 + (tap % 5); }
        kOff[p] = v;
    }
    int ro[2][2], mm[2][2];
#pragma unroll
    for (int t = 0; t < 2; t++)
#pragma unroll
        for (int h = 0; h < 2; h++) {
            int m = wid * 32 + t * 16 + gid + h * 8;
            mm[t][h] = m;
            ro[t][h] = (m >> 7) * 132 + (m & 127);
        }
    __syncthreads();

    float acc[2][8][4];
#pragma unroll
    for (int t = 0; t < 2; t++)
#pragma unroll
        for (int nt = 0; nt < 8; nt++)
#pragma unroll
            for (int j = 0; j < 4; j++) acc[t][nt][j] = 0.f;

    for (int kcl = 0; kcl < 40; kcl++) {
        uint32_t ko0 = kOff[kcl * 8 + tig], ko1 = kOff[kcl * 8 + tig + 4];
        uint32_t aH[2][4], aL[2][4];
#pragma unroll
        for (int t = 0; t < 2; t++) {
            ull p00 = s64[ko0 + ro[t][0]], p01 = s64[ko0 + ro[t][1]];
            ull p10 = s64[ko1 + ro[t][0]], p11 = s64[ko1 + ro[t][1]];
            aH[t][0] = (uint32_t)p00;  aL[t][0] = (uint32_t)(p00 >> 32);
            aH[t][1] = (uint32_t)p01;  aL[t][1] = (uint32_t)(p01 >> 32);
            aH[t][2] = (uint32_t)p10;  aL[t][2] = (uint32_t)(p10 >> 32);
            aH[t][3] = (uint32_t)p11;  aL[t][3] = (uint32_t)(p11 >> 32);
        }
#pragma unroll
        for (int nt = 0; nt < 8; nt++) {
            uint2 bd = __ldg(&g_Bc[(kcl * 8 + nt) * 32 + lane]);
#pragma unroll
            for (int t = 0; t < 2; t++) {
                mma_f16(acc[t][nt], aH[t], bd.x, bd.y);
                mma_f16(acc[t][nt], aL[t], bd.x, bd.y);
            }
        }
    }
#pragma unroll
    for (int t = 0; t < 2; t++)
#pragma unroll
        for (int nt = 0; nt < 8; nt++) {
            int n0 = nt * 8 + tig * 2;
            int cp = n0 >> 1;
#pragma unroll
            for (int h = 0; h < 2; h++) {
                int m = mm[t][h];
                int row = gy0 + (m >> 7), col = gx0 + (m & 127);
                if (row < W2F && col < W2F && n0 < 60) {
                    float v0 = acc[t][nt][h * 2]     + __ldg(&bias[n0]);
                    float v1 = acc[t][nt][h * 2 + 1] + __ldg(&bias[n0 + 1]);
                    H2[(size_t)cp * H2SZ + row * W2F + col] =
                        hl64(fmaxf(v0, 0.f), fmaxf(v1, 0.f));
                }
            }
        }
}

// ---------------- K3: deconv2 per-patch GEMM (fp16 2-term), K-split x M-split ----------------
// smem: s64[7800] u64 + kOff[384] u32 = 63936 B
#define D2_PS 7800
#define D2_SMEM (D2_PS * 8 + 384 * 4)
__global__ void __launch_bounds__(320, 2)
deconv2_mma_kernel(const ull* __restrict__ H2, const float* __restrict__ bias,
                   float* __restrict__ part) {
    extern __shared__ ull s64[];
    uint32_t* kOff = (uint32_t*)(s64 + D2_PS);
    const int cta = blockIdx.x;
    const int n = cta >> 2, half = (cta >> 1) & 1, mhalf = cta & 1;
    const int gy0 = (n / NHH) * 16, gx0 = (n % NHH) * 16;
    const int tid = threadIdx.x, lane = tid & 31, wid = tid >> 5;
    const int gid = lane >> 2, tig = lane & 3;

    for (int i = tid; i < D2_PS; i += 320) s64[i] = 0ull;
    for (int p = tid; p < 384; p += 320) {
        int k = 2 * p;
        uint32_t v = 7395u;
        if (k < 750) { int tap = k / 30, cp = (k % 30) >> 1;
                       v = cp * 493 + (tap / 5) * 29 + (tap % 5); }
        kOff[p] = v;
    }
    __syncthreads();
    // stage 13-row window: mhalf0 -> patch y 0..12 at l=y+4; mhalf1 -> patch y 8..20 at l=y-8
    for (int i = tid; i < 15 * 13 * 21; i += 320) {
        int cp = i / 273, rem = i % 273, lr = rem / 21, c = rem % 21;
        int l = lr + (mhalf ? 0 : 4);
        int y = l + mhalf * 12 - 4;
        s64[cp * 493 + l * 29 + (c + 4)] =
            H2[(size_t)(half * 15 + cp) * H2SZ + (gy0 + y) * W2F + (gx0 + c)];
    }
    int ro[2][2], mm[2][2];
#pragma unroll
    for (int t = 0; t < 2; t++)
#pragma unroll
        for (int h = 0; h < 2; h++) {
            int m = mhalf * 320 + wid * 32 + t * 16 + gid + h * 8;
            mm[t][h] = m;
            ro[t][h] = (m / 25 - mhalf * 12) * 29 + (m % 25);
        }
    __syncthreads();

    float acc[2][3][4];
#pragma unroll
    for (int t = 0; t < 2; t++)
#pragma unroll
        for (int nt = 0; nt < 3; nt++)
#pragma unroll
            for (int j = 0; j < 4; j++) acc[t][nt][j] = 0.f;

    for (int kcl = 0; kcl < 48; kcl++) {
        uint32_t ko0 = kOff[kcl * 8 + tig], ko1 = kOff[kcl * 8 + tig + 4];
        uint32_t aH[2][4], aL[2][4];
#pragma unroll
        for (int t = 0; t < 2; t++) {
            ull p00 = s64[ko0 + ro[t][0]], p01 = s64[ko0 + ro[t][1]];
            ull p10 = s64[ko1 + ro[t][0]], p11 = s64[ko1 + ro[t][1]];
            aH[t][0] = (uint32_t)p00;  aL[t][0] = (uint32_t)(p00 >> 32);
            aH[t][1] = (uint32_t)p01;  aL[t][1] = (uint32_t)(p01 >> 32);
            aH[t][2] = (uint32_t)p10;  aL[t][2] = (uint32_t)(p10 >> 32);
            aH[t][3] = (uint32_t)p11;  aL[t][3] = (uint32_t)(p11 >> 32);
        }
#pragma unroll
        for (int nt = 0; nt < 3; nt++) {
            uint2 bd = __ldg(&g_Bd[((half * 48 + kcl) * 3 + nt) * 32 + lane]);
#pragma unroll
            for (int t = 0; t < 2; t++) {
                mma_f16(acc[t][nt], aH[t], bd.x, bd.y);
                mma_f16(acc[t][nt], aL[t], bd.x, bd.y);
            }
        }
    }
    float* pb = part + ((size_t)half * NP + n) * 15000;
#pragma unroll
    for (int t = 0; t < 2; t++)
#pragma unroll
        for (int nt = 0; nt < 3; nt++) {
            int n0 = nt * 8 + tig * 2;
#pragma unroll
            for (int h = 0; h < 2; h++) {
                int m = mm[t][h];
                if (m < 625) {
                    float v0 = acc[t][nt][h * 2]     + (half ? 0.f : __ldg(&bias[n0]));
                    float v1 = acc[t][nt][h * 2 + 1] + (half ? 0.f : __ldg(&bias[n0 + 1]));
                    reinterpret_cast<float2*>(pb)[(n0 >> 1) * 625 + m] = make_float2(v0, v1);
                }
            }
        }
}

// ---------------- K4: reduce partials + ELU + deconv1 + einsum (FFMA2), y-split occ2 ----------------
#define K4_SMEM 92256
__global__ void __launch_bounds__(256, 2)
deconv1_p_kernel(const float* __restrict__ part, const float* __restrict__ w1,
                 const float* __restrict__ b1, const float* __restrict__ lin_w,
                 const float* __restrict__ lin_b, float* __restrict__ P) {
    extern __shared__ ull sm[];
    ull* sIn = sm;  // 12*897 = 10764
    float2* sWf = reinterpret_cast<float2*>(sm + 10764);
    const int bid = blockIdx.x;
    const int n = bid >> 1, half = bid & 1;
    const float lw0 = lin_w[2 * n], lw1 = lin_w[2 * n + 1];
    for (int i = threadIdx.x; i < 10764; i += 256) sIn[i] = 0ull;
    __syncthreads();
    const float2* p0 = reinterpret_cast<const float2*>(part + (size_t)n * 15000);
    const float2* p1 = reinterpret_cast<const float2*>(part + ((size_t)NP + n) * 15000);
    for (int i = threadIdx.x; i < 12 * 16 * 25; i += 256) {
        int cp = i / 400, rem = i % 400, lr = rem / 25, x = rem % 25;
        int img_y = lr + (half ? 9 : 0);
        int l = img_y + 7 - half * 16;
        float2 a = p0[cp * 625 + img_y * 25 + x], b = p1[cp * 625 + img_y * 25 + x];
        float vx = elu1(a.x + b.x), vy = elu1(a.y + b.y);
        sIn[cp * 897 + l * 39 + x + 7] =
            ((ull)__float_as_uint(vy) << 32) | (ull)__float_as_uint(vx);
    }
    for (int i = threadIdx.x; i < 768; i += 256) {
        int cp = i >> 6, rem = i & 63;
        int ky = rem >> 3, kx = rem & 7;
        int f0 = (2 * cp) * 128 + (7 - ky) * 8 + (7 - kx);
        int f1 = (2 * cp + 1) * 128 + (7 - ky) * 8 + (7 - kx);
        sWf[i] = make_float2(lw0 * w1[f0] + lw1 * w1[f0 + 64],
                             lw0 * w1[f1] + lw1 * w1[f1 + 64]);
    }
    __syncthreads();
    const ull* sW = reinterpret_cast<const ull*>(sWf);
    const float cst = (lw0 + lw1) * b1[0] + lin_b[n];
    const int t = threadIdx.x;
    const int yl = t >> 4;
    const int x0 = (t & 15) * 2;
    ull acc0 = 0ull, acc1 = 0ull;
    for (int cp = 0; cp < 12; cp++) {
#pragma unroll
        for (int ky = 0; ky < 8; ky++) {
            ull reg[9];
            const ull* row = sIn + cp * 897 + (yl + ky) * 39 + x0;
#pragma unroll
            for (int i = 0; i < 9; i++) reg[i] = row[i];
            const ull* wr = sW + cp * 64 + ky * 8;
#pragma unroll
            for (int kx = 0; kx < 8; kx++) {
                ull wv = wr[kx];
                fma2(acc0, reg[kx], wv);
                fma2(acc1, reg[kx + 1], wv);
            }
        }
    }
    float* outp = P + (size_t)n * 1024 + (half * 16 + yl) * 32 + x0;
    outp[0] = lo_f(acc0) + hi_f(acc0) + cst;
    outp[1] = lo_f(acc1) + hi_f(acc1) + cst;
}

// ---------------- K5: overlap-add + residual ----------------
__global__ void final_kernel(const float* __restrict__ x2, const float* __restrict__ P,
                             const float* __restrict__ linear1_w, float* __restrict__ out) {
    int idx = blockIdx.x * blockDim.x + threadIdx.x;
    if (idx >= HH * WW) return;
    int Y = idx >> 10, X = idx & 1023;
    float s = 0.f;
    int iy = Y >> 4, ix = X >> 4;
#pragma unroll
    for (int di = 0; di < 2; di++) {
        int i = iy - di;
        if (i < 0 || i > 62) continue;
        int py = Y - i * 16;
        if (py >= 32) continue;
#pragma unroll
        for (int dj = 0; dj < 2; dj++) {
            int j = ix - dj;
            if (j < 0 || j > 62) continue;
            int px = X - j * 16;
            if (px >= 32) continue;
            s += P[(size_t)(i * NHH + j) * 1024 + py * 32 + px];
        }
    }
    out[idx] = x2[idx] - s * linear1_w[0];
}

// ---------------------------------------------------------------------------
extern "C" void kernel_launch(void* const* d_in, const int* in_sizes, int n_in,
                              void* d_out, int out_size) {
    const float* x1        = (const float*)d_in[0];
    const float* x2        = (const float*)d_in[1];
    const float* conv1_w   = (const float*)d_in[2];
    const float* conv1_b   = (const float*)d_in[3];
    const float* conv2_w   = (const float*)d_in[4];
    const float* conv2_b   = (const float*)d_in[5];
    const float* deconv2_w = (const float*)d_in[6];
    const float* deconv2_b = (const float*)d_in[7];
    const float* deconv1_w = (const float*)d_in[8];
    const float* deconv1_b = (const float*)d_in[9];
    const float* lin_w     = (const float*)d_in[10];
    const float* lin_b     = (const float*)d_in[11];
    const float* linear1_w = (const float*)d_in[12];
    float* out = (float*)d_out;

    ull *H1, *H2;
    float *part, *P;
    cudaGetSymbolAddress((void**)&H1,   g_H1);
    cudaGetSymbolAddress((void**)&H2,   g_H2);
    cudaGetSymbolAddress((void**)&part, g_part);
    cudaGetSymbolAddress((void**)&P,    g_p);

    cudaFuncSetAttribute(conv2_full_kernel,  cudaFuncAttributeMaxDynamicSharedMemorySize, C2_SMEM);
    cudaFuncSetAttribute(deconv2_mma_kernel, cudaFuncAttributeMaxDynamicSharedMemorySize, D2_SMEM);
    cudaFuncSetAttribute(deconv1_p_kernel,   cudaFuncAttributeMaxDynamicSharedMemorySize, K4_SMEM);

    pack_kernel<<<(10240 + 9216 + 255) / 256, 256>>>(conv2_w, deconv2_w);
    conv1_full_kernel<<<dim3(16, 64), 256>>>(x1, x2, conv1_w, conv1_b, H1);
    conv2_full_kernel<<<507 * 8, 256, C2_SMEM>>>(H1, conv2_b, H2);
    deconv2_mma_kernel<<<NP * 4, 320, D2_SMEM>>>(H2, deconv2_b, part);
    deconv1_p_kernel<<<NP * 2, 256, K4_SMEM>>>(part, deconv1_w, deconv1_b, lin_w, lin_b, P);
    final_kernel<<<(HH * WW + 255) / 256, 256>>>(x2, P, linear1_w, out);
}

// round 16
// speedup vs baseline: 4.6939x; 1.3783x over previous
#include <cuda_runtime.h>
#include <cuda_fp16.h>
#include <math.h>
#include <stdint.h>

#define HH 1024
#define WW 1024
#define NHH 63
#define NP 3969
#define W1F 1017
#define W2F 1013
#define H1SZ (W1F * W1F)
#define H2SZ (W2F * W2F)

typedef unsigned long long ull;

// -------- global intermediates --------
// channel-pair fp16 planes (single precision term): u32 = fp16(c) | fp16(c+1)<<16
__device__ uint32_t g_H1[(size_t)12 * H1SZ];
__device__ uint32_t g_H2[(size_t)30 * H2SZ];
__device__ float    g_h3[(size_t)NP * 15000];    // deconv2 out, channel-paired float2
__device__ float    g_p[(size_t)NP * 1024];
__device__ uint2    g_Bc[40 * 8 * 32];           // conv2 B frags (fp16)
__device__ uint2    g_Bd2[96 * 3 * 32];          // deconv2 B frags (fp16, full K)

__device__ __forceinline__ float elu1(float v) { return v > 0.f ? v : expm1f(v); }
__device__ __forceinline__ uint32_t hpack(float a, float b) {
    return (uint32_t)__half_as_ushort(__float2half(a)) |
           ((uint32_t)__half_as_ushort(__float2half(b)) << 16);
}
__device__ __forceinline__ void fma2(ull &d, ull a, ull b) {
    asm("fma.rn.f32x2 %0, %1, %2, %0;" : "+l"(d) : "l"(a), "l"(b));
}
__device__ __forceinline__ float lo_f(ull u) { return __uint_as_float((unsigned)u); }
__device__ __forceinline__ float hi_f(ull u) { return __uint_as_float((unsigned)(u >> 32)); }

__device__ __forceinline__ void mma_f16(float d[4], const uint32_t a[4],
                                        uint32_t b0, uint32_t b1) {
    asm("mma.sync.aligned.m16n8k16.row.col.f32.f16.f16.f32 "
        "{%0,%1,%2,%3}, {%4,%5,%6,%7}, {%8,%9}, {%0,%1,%2,%3};"
        : "+f"(d[0]), "+f"(d[1]), "+f"(d[2]), "+f"(d[3])
        : "r"(a[0]), "r"(a[1]), "r"(a[2]), "r"(a[3]), "r"(b0), "r"(b1));
}

// ---------------- K0: pack B frag tables ----------------
__global__ void pack_kernel(const float* __restrict__ w2, const float* __restrict__ wd2) {
    int j = blockIdx.x * blockDim.x + threadIdx.x;
    if (j < 10240) {
        // conv2: idx=(kcl*8+nt)*32+lane; k = tap*24+ci, K=600 pad 640
        int lane = j & 31, nt = (j >> 5) & 7, kcl = j >> 8;
        int gid = lane >> 2, tig = lane & 3;
        int n = nt * 8 + gid;
        uint32_t fr[2];
#pragma unroll
        for (int s = 0; s < 2; s++) {
            int k = kcl * 16 + 2 * tig + s * 8;
            float v0 = 0.f, v1 = 0.f;
            if (n < 60 && k < 600) {
                int tap = k / 24, ci = k % 24;
                v0 = w2[n * 600 + ci * 25 + tap];
                v1 = w2[n * 600 + (ci + 1) * 25 + tap];
            }
            fr[s] = hpack(v0, v1);
        }
        g_Bc[j] = make_uint2(fr[0], fr[1]);
    } else if (j < 10240 + 9216) {
        // deconv2 full-K: idx=(kcl*3+nt)*32+lane; k = tap*60+ci, K=1500 pad 1536
        int i = j - 10240;
        int lane = i & 31, nt = (i >> 5) % 3, kcl = i / 96;
        int gid = lane >> 2, tig = lane & 3;
        int r = nt * 8 + gid;   // < 24
        uint32_t fr[2];
#pragma unroll
        for (int s = 0; s < 2; s++) {
            int k = kcl * 16 + 2 * tig + s * 8;
            float v0 = 0.f, v1 = 0.f;
            if (k < 1500) {
                int tap = k / 60, ci = k % 60;
                v0 = wd2[ci * 600 + r * 25 + (24 - tap)];
                v1 = wd2[(ci + 1) * 600 + r * 25 + (24 - tap)];
            }
            fr[s] = hpack(v0, v1);
        }
        g_Bd2[i] = make_uint2(fr[0], fr[1]);
    }
}

// ---------------- K1: conv1 full-image (FFMA2) -> fp16 pair planes ----------------
__global__ void __launch_bounds__(256)
conv1_full_kernel(const float* __restrict__ x1, const float* __restrict__ x2,
                  const float* __restrict__ w, const float* __restrict__ b,
                  uint32_t* __restrict__ H1) {
    __shared__ float2 sImg[23 * 72];
    __shared__ float2 sW2[24 * 64];
    __shared__ float sB[24];
    const int gy0 = blockIdx.y * 16, gx0 = blockIdx.x * 64;
    const int tid = threadIdx.x;
    for (int i = tid; i < 23 * 72; i += 256) {
        int r = i / 72, c = i % 72;
        int gy = gy0 + r, gx = gx0 + c;
        float2 v = make_float2(0.f, 0.f);
        if (c < 71 && gy < 1024 && gx < 1024) {
            int g = gy * 1024 + gx;
            v = make_float2(x1[g], x2[g]);
        }
        sImg[i] = v;
    }
    for (int i = tid; i < 1536; i += 256) {
        int c = i >> 6, rem = i & 63;
        sW2[i] = make_float2(w[c * 128 + rem], w[c * 128 + 64 + rem]);
    }
    if (tid < 24) sB[tid] = b[tid];
    __syncthreads();
    const ull* sP = reinterpret_cast<const ull*>(sImg);
    const ull* sW = reinterpret_cast<const ull*>(sW2);
    const int y = tid >> 4, x0 = (tid & 15) * 4;
    const int gy = gy0 + y;
    for (int c0 = 0; c0 < 24; c0 += 4) {
        ull acc[4][4];
#pragma unroll
        for (int cc = 0; cc < 4; cc++)
#pragma unroll
            for (int j = 0; j < 4; j++) acc[cc][j] = 0ull;
#pragma unroll
        for (int ky = 0; ky < 8; ky++) {
            ull reg[11];
            const ull* row = sP + (y + ky) * 72 + x0;
#pragma unroll
            for (int i = 0; i < 11; i++) reg[i] = row[i];
#pragma unroll
            for (int cc = 0; cc < 4; cc++) {
                const ull* wr = sW + (c0 + cc) * 64 + ky * 8;
#pragma unroll
                for (int kx = 0; kx < 8; kx++) {
                    ull wv = wr[kx];
#pragma unroll
                    for (int j = 0; j < 4; j++) fma2(acc[cc][j], reg[j + kx], wv);
                }
            }
        }
        if (gy < W1F) {
#pragma unroll
            for (int pp = 0; pp < 2; pp++) {
                int cp = (c0 >> 1) + pp;
                float b0 = sB[c0 + 2 * pp], b1 = sB[c0 + 2 * pp + 1];
#pragma unroll
                for (int j = 0; j < 4; j++) {
                    int gx = gx0 + x0 + j;
                    if (gx < W1F) {
                        float v0 = elu1(lo_f(acc[2 * pp][j]) + hi_f(acc[2 * pp][j]) + b0);
                        float v1 = elu1(lo_f(acc[2 * pp + 1][j]) + hi_f(acc[2 * pp + 1][j]) + b1);
                        H1[(size_t)cp * H1SZ + gy * W1F + gx] = hpack(v0, v1);
                    }
                }
            }
        }
    }
}

// ---------------- K2: conv2 full-image GEMM (fp16 1-term) -> H2 ----------------
// smem u32: s32[9768] + kOff[320] = 40352 B
#define C2_PS 9768
#define C2_SMEM (C2_PS * 4 + 320 * 4)
__global__ void __launch_bounds__(256, 2)
conv2_full_kernel(const uint32_t* __restrict__ H1, const float* __restrict__ bias,
                  uint32_t* __restrict__ H2) {
    extern __shared__ uint32_t s32[];
    uint32_t* kOff = s32 + C2_PS;
    const int bid = blockIdx.x;
    const int gy0 = (bid >> 3) * 2, gx0 = (bid & 7) * 128;
    const int tid = threadIdx.x, lane = tid & 31, wid = tid >> 5;
    const int gid = lane >> 2, tig = lane & 3;

    for (int i = tid; i < C2_PS; i += 256) {
        uint32_t v = 0u;
        if (i < 9504) {
            int cp = i / 792, rem = i % 792, r = rem / 132, c = rem % 132;
            int gy = gy0 + r, gx = gx0 + c;
            if (gy < W1F && gx < W1F) v = H1[(size_t)cp * H1SZ + gy * W1F + gx];
        }
        s32[i] = v;
    }
    for (int p = tid; p < 320; p += 256) {
        int k = 2 * p;
        uint32_t v = 9504u;
        if (k < 600) { int tap = k / 24, cp = (k % 24) >> 1;
                       v = cp * 792 + (tap / 5) * 132 + (tap % 5); }
        kOff[p] = v;
    }
    int ro[2][2], mm[2][2];
#pragma unroll
    for (int t = 0; t < 2; t++)
#pragma unroll
        for (int h = 0; h < 2; h++) {
            int m = wid * 32 + t * 16 + gid + h * 8;
            mm[t][h] = m;
            ro[t][h] = (m >> 7) * 132 + (m & 127);
        }
    __syncthreads();

    float acc[2][8][4];
#pragma unroll
    for (int t = 0; t < 2; t++)
#pragma unroll
        for (int nt = 0; nt < 8; nt++)
#pragma unroll
            for (int j = 0; j < 4; j++) acc[t][nt][j] = 0.f;

    for (int kcl = 0; kcl < 40; kcl++) {
        uint32_t ko0 = kOff[kcl * 8 + tig], ko1 = kOff[kcl * 8 + tig + 4];
        uint32_t a[2][4];
#pragma unroll
        for (int t = 0; t < 2; t++) {
            a[t][0] = s32[ko0 + ro[t][0]];
            a[t][1] = s32[ko0 + ro[t][1]];
            a[t][2] = s32[ko1 + ro[t][0]];
            a[t][3] = s32[ko1 + ro[t][1]];
        }
#pragma unroll
        for (int nt = 0; nt < 8; nt++) {
            uint2 bd = __ldg(&g_Bc[(kcl * 8 + nt) * 32 + lane]);
#pragma unroll
            for (int t = 0; t < 2; t++)
                mma_f16(acc[t][nt], a[t], bd.x, bd.y);
        }
    }
#pragma unroll
    for (int t = 0; t < 2; t++)
#pragma unroll
        for (int nt = 0; nt < 8; nt++) {
            int n0 = nt * 8 + tig * 2;
            int cp = n0 >> 1;
#pragma unroll
            for (int h = 0; h < 2; h++) {
                int m = mm[t][h];
                int row = gy0 + (m >> 7), col = gx0 + (m & 127);
                if (row < W2F && col < W2F && n0 < 60) {
                    float v0 = acc[t][nt][h * 2]     + __ldg(&bias[n0]);
                    float v1 = acc[t][nt][h * 2 + 1] + __ldg(&bias[n0 + 1]);
                    H2[(size_t)cp * H2SZ + row * W2F + col] =
                        hpack(fmaxf(v0, 0.f), fmaxf(v1, 0.f));
                }
            }
        }
}

// ---------------- K3: deconv2 per-patch GEMM (fp16 1-term), FULL K, M-split only ----------------
// staged planes: 30 cp x 493 u32 (17 l-rows x 29) = 14790, pad to 15232; kOff[768]
// smem = (15232 + 768) * 4 = 64000 B
#define D2_PS 15232
#define D2_SMEM ((D2_PS + 768) * 4)
__global__ void __launch_bounds__(320, 2)
deconv2_mma_kernel(const uint32_t* __restrict__ H2, const float* __restrict__ bias,
                   float* __restrict__ h3) {
    extern __shared__ uint32_t s32[];
    uint32_t* kOff = s32 + D2_PS;
    const int cta = blockIdx.x;
    const int n = cta >> 1, mhalf = cta & 1;
    const int gy0 = (n / NHH) * 16, gx0 = (n % NHH) * 16;
    const int tid = threadIdx.x, lane = tid & 31, wid = tid >> 5;
    const int gid = lane >> 2, tig = lane & 3;

    for (int i = tid; i < D2_PS; i += 320) s32[i] = 0u;
    for (int p = tid; p < 768; p += 320) {
        int k = 2 * p;
        uint32_t v = 14790u;
        if (k < 1500) { int tap = k / 60, cp = (k % 60) >> 1;
                        v = cp * 493 + (tap / 5) * 29 + (tap % 5); }
        kOff[p] = v;
    }
    __syncthreads();
    // stage 13-row data window, all 30 planes:
    // mhalf0 -> patch y 0..12 at l=y+4; mhalf1 -> patch y 8..20 at l=y-8
    for (int i = tid; i < 30 * 13 * 21; i += 320) {
        int cp = i / 273, rem = i % 273, lr = rem / 21, c = rem % 21;
        int l = lr + (mhalf ? 0 : 4);
        int y = l + mhalf * 12 - 4;
        s32[cp * 493 + l * 29 + (c + 4)] =
            H2[(size_t)cp * H2SZ + (gy0 + y) * W2F + (gx0 + c)];
    }
    int ro[2][2], mm[2][2];
#pragma unroll
    for (int t = 0; t < 2; t++)
#pragma unroll
        for (int h = 0; h < 2; h++) {
            int m = mhalf * 320 + wid * 32 + t * 16 + gid + h * 8;
            mm[t][h] = m;
            ro[t][h] = (m / 25 - mhalf * 12) * 29 + (m % 25);
        }
    __syncthreads();

    float acc[2][3][4];
#pragma unroll
    for (int t = 0; t < 2; t++)
#pragma unroll
        for (int nt = 0; nt < 3; nt++)
#pragma unroll
            for (int j = 0; j < 4; j++) acc[t][nt][j] = 0.f;

    for (int kcl = 0; kcl < 96; kcl++) {
        uint32_t ko0 = kOff[kcl * 8 + tig], ko1 = kOff[kcl * 8 + tig + 4];
        uint32_t a[2][4];
#pragma unroll
        for (int t = 0; t < 2; t++) {
            a[t][0] = s32[ko0 + ro[t][0]];
            a[t][1] = s32[ko0 + ro[t][1]];
            a[t][2] = s32[ko1 + ro[t][0]];
            a[t][3] = s32[ko1 + ro[t][1]];
        }
#pragma unroll
        for (int nt = 0; nt < 3; nt++) {
            uint2 bd = __ldg(&g_Bd2[(kcl * 3 + nt) * 32 + lane]);
#pragma unroll
            for (int t = 0; t < 2; t++)
                mma_f16(acc[t][nt], a[t], bd.x, bd.y);
        }
    }
    float* pb = h3 + (size_t)n * 15000;
#pragma unroll
    for (int t = 0; t < 2; t++)
#pragma unroll
        for (int nt = 0; nt < 3; nt++) {
            int n0 = nt * 8 + tig * 2;   // 0..22
#pragma unroll
            for (int h = 0; h < 2; h++) {
                int m = mm[t][h];
                if (m < 625) {
                    float v0 = elu1(acc[t][nt][h * 2]     + __ldg(&bias[n0]));
                    float v1 = elu1(acc[t][nt][h * 2 + 1] + __ldg(&bias[n0 + 1]));
                    reinterpret_cast<float2*>(pb)[(n0 >> 1) * 625 + m] = make_float2(v0, v1);
                }
            }
        }
}

// ---------------- K4: deconv1 + einsum + bias (FFMA2), y-split occ2 ----------------
#define K4_SMEM 92256
__global__ void __launch_bounds__(256, 2)
deconv1_p_kernel(const float* __restrict__ h3, const float* __restrict__ w1,
                 const float* __restrict__ b1, const float* __restrict__ lin_w,
                 const float* __restrict__ lin_b, float* __restrict__ P) {
    extern __shared__ ull sm[];
    ull* sIn = sm;  // 12*897 = 10764
    float2* sWf = reinterpret_cast<float2*>(sm + 10764);
    const int bid = blockIdx.x;
    const int n = bid >> 1, half = bid & 1;
    const float lw0 = lin_w[2 * n], lw1 = lin_w[2 * n + 1];
    for (int i = threadIdx.x; i < 10764; i += 256) sIn[i] = 0ull;
    __syncthreads();
    const float2* p0 = reinterpret_cast<const float2*>(h3 + (size_t)n * 15000);
    for (int i = threadIdx.x; i < 12 * 16 * 25; i += 256) {
        int cp = i / 400, rem = i % 400, lr = rem / 25, x = rem % 25;
        int img_y = lr + (half ? 9 : 0);
        int l = img_y + 7 - half * 16;
        float2 a = p0[cp * 625 + img_y * 25 + x];
        sIn[cp * 897 + l * 39 + x + 7] =
            ((ull)__float_as_uint(a.y) << 32) | (ull)__float_as_uint(a.x);
    }
    for (int i = threadIdx.x; i < 768; i += 256) {
        int cp = i >> 6, rem = i & 63;
        int ky = rem >> 3, kx = rem & 7;
        int f0 = (2 * cp) * 128 + (7 - ky) * 8 + (7 - kx);
        int f1 = (2 * cp + 1) * 128 + (7 - ky) * 8 + (7 - kx);
        sWf[i] = make_float2(lw0 * w1[f0] + lw1 * w1[f0 + 64],
                             lw0 * w1[f1] + lw1 * w1[f1 + 64]);
    }
    __syncthreads();
    const ull* sW = reinterpret_cast<const ull*>(sWf);
    const float cst = (lw0 + lw1) * b1[0] + lin_b[n];
    const int t = threadIdx.x;
    const int yl = t >> 4;
    const int x0 = (t & 15) * 2;
    ull acc0 = 0ull, acc1 = 0ull;
    for (int cp = 0; cp < 12; cp++) {
#pragma unroll
        for (int ky = 0; ky < 8; ky++) {
            ull reg[9];
            const ull* row = sIn + cp * 897 + (yl + ky) * 39 + x0;
#pragma unroll
            for (int i = 0; i < 9; i++) reg[i] = row[i];
            const ull* wr = sW + cp * 64 + ky * 8;
#pragma unroll
            for (int kx = 0; kx < 8; kx++) {
                ull wv = wr[kx];
                fma2(acc0, reg[kx], wv);
                fma2(acc1, reg[kx + 1], wv);
            }
        }
    }
    float* outp = P + (size_t)n * 1024 + (half * 16 + yl) * 32 + x0;
    outp[0] = lo_f(acc0) + hi_f(acc0) + cst;
    outp[1] = lo_f(acc1) + hi_f(acc1) + cst;
}

// ---------------- K5: overlap-add + residual ----------------
__global__ void final_kernel(const float* __restrict__ x2, const float* __restrict__ P,
                             const float* __restrict__ linear1_w, float* __restrict__ out) {
    int idx = blockIdx.x * blockDim.x + threadIdx.x;
    if (idx >= HH * WW) return;
    int Y = idx >> 10, X = idx & 1023;
    float s = 0.f;
    int iy = Y >> 4, ix = X >> 4;
#pragma unroll
    for (int di = 0; di < 2; di++) {
        int i = iy - di;
        if (i < 0 || i > 62) continue;
        int py = Y - i * 16;
        if (py >= 32) continue;
#pragma unroll
        for (int dj = 0; dj < 2; dj++) {
            int j = ix - dj;
            if (j < 0 || j > 62) continue;
            int px = X - j * 16;
            if (px >= 32) continue;
            s += P[(size_t)(i * NHH + j) * 1024 + py * 32 + px];
        }
    }
    out[idx] = x2[idx] - s * linear1_w[0];
}

// ---------------------------------------------------------------------------
extern "C" void kernel_launch(void* const* d_in, const int* in_sizes, int n_in,
                              void* d_out, int out_size) {
    const float* x1        = (const float*)d_in[0];
    const float* x2        = (const float*)d_in[1];
    const float* conv1_w   = (const float*)d_in[2];
    const float* conv1_b   = (const float*)d_in[3];
    const float* conv2_w   = (const float*)d_in[4];
    const float* conv2_b   = (const float*)d_in[5];
    const float* deconv2_w = (const float*)d_in[6];
    const float* deconv2_b = (const float*)d_in[7];
    const float* deconv1_w = (const float*)d_in[8];
    const float* deconv1_b = (const float*)d_in[9];
    const float* lin_w     = (const float*)d_in[10];
    const float* lin_b     = (const float*)d_in[11];
    const float* linear1_w = (const float*)d_in[12];
    float* out = (float*)d_out;

    uint32_t *H1, *H2;
    float *h3, *P;
    cudaGetSymbolAddress((void**)&H1, g_H1);
    cudaGetSymbolAddress((void**)&H2, g_H2);
    cudaGetSymbolAddress((void**)&h3, g_h3);
    cudaGetSymbolAddress((void**)&P,  g_p);

    cudaFuncSetAttribute(conv2_full_kernel,  cudaFuncAttributeMaxDynamicSharedMemorySize, C2_SMEM);
    cudaFuncSetAttribute(deconv2_mma_kernel, cudaFuncAttributeMaxDynamicSharedMemorySize, D2_SMEM);
    cudaFuncSetAttribute(deconv1_p_kernel,   cudaFuncAttributeMaxDynamicSharedMemorySize, K4_SMEM);

    pack_kernel<<<(10240 + 9216 + 255) / 256, 256>>>(conv2_w, deconv2_w);
    conv1_full_kernel<<<dim3(16, 64), 256>>>(x1, x2, conv1_w, conv1_b, H1);
    conv2_full_kernel<<<507 * 8, 256, C2_SMEM>>>(H1, conv2_b, H2);
    deconv2_mma_kernel<<<NP * 2, 320, D2_SMEM>>>(H2, deconv2_b, h3);
    deconv1_p_kernel<<<NP * 2, 256, K4_SMEM>>>(h3, deconv1_w, deconv1_b, lin_w, lin_b, P);
    final_kernel<<<(HH * WW + 255) / 256, 256>>>(x2, P, linear1_w, out);
}